// round 1
// baseline (speedup 1.0000x reference)
#include <cuda_runtime.h>

#define N_NODES 100000
#define N_EDGES 1600000
// dims: IN=128, HIDDEN=128, OUT=64

// ---------------- scratch (device globals: allocation-free) ----------------
__device__ int   g_cnt[N_NODES];
__device__ int   g_off[N_NODES];
__device__ int   g_pos[N_NODES];
__device__ float g_inv[N_NODES];
__device__ int   g_csr[N_EDGES];
__device__ float g_hn [N_NODES * 128];   // layer1 aggregated (pre-GEMM1)
__device__ float g_h1 [N_NODES * 128];   // relu(GEMM1)
__device__ float g_y2 [N_NODES * 64];    // GEMM2 output (pre-aggregation)

// ---------------- CSR build ----------------
__global__ void k_zero_cnt() {
    int i = blockIdx.x * blockDim.x + threadIdx.x;
    if (i < N_NODES) g_cnt[i] = 0;
}

__global__ void k_hist(const int* __restrict__ dst) {
    int e = blockIdx.x * blockDim.x + threadIdx.x;
    if (e < N_EDGES) atomicAdd(&g_cnt[dst[e]], 1);
}

// single-block exclusive scan of g_cnt -> g_off (+ g_pos copy, g_inv)
__global__ void k_scan() {
    __shared__ int sh[1024];
    const int t = threadIdx.x;
    const int CH = (N_NODES + 1023) / 1024;   // 98
    const int base = t * CH;
    int s = 0;
    for (int i = 0; i < CH; i++) {
        int idx = base + i;
        if (idx < N_NODES) s += g_cnt[idx];
    }
    sh[t] = s;
    __syncthreads();
    for (int off = 1; off < 1024; off <<= 1) {
        int v = 0;
        if (t >= off) v = sh[t - off];
        __syncthreads();
        sh[t] += v;
        __syncthreads();
    }
    int run = (t == 0) ? 0 : sh[t - 1];
    for (int i = 0; i < CH; i++) {
        int idx = base + i;
        if (idx < N_NODES) {
            g_off[idx] = run;
            g_pos[idx] = run;
            int c = g_cnt[idx];
            g_inv[idx] = 1.0f / (float)(c + 1);
            run += c;
        }
    }
}

__global__ void k_fill(const int* __restrict__ src, const int* __restrict__ dst) {
    int e = blockIdx.x * blockDim.x + threadIdx.x;
    if (e < N_EDGES) {
        int p = atomicAdd(&g_pos[dst[e]], 1);
        g_csr[p] = src[e];
    }
}

// ---------------- aggregation: out[n] = (sum_{s->n} x[s] + x[n]) * inv[n] (+bias) ----
// One thread per (node, float4-chunk). DIMS4 = row width / 4.
template <int DIMS4, bool BIAS>
__global__ void k_agg(const float4* __restrict__ x,
                      const float*  __restrict__ bias,
                      float4*       __restrict__ out) {
    long long t = (long long)blockIdx.x * blockDim.x + threadIdx.x;
    int node = (int)(t / DIMS4);
    int c    = (int)(t % DIMS4);
    if (node >= N_NODES) return;

    const int start = g_off[node];
    const int cnt   = g_cnt[node];

    float4 acc = x[(long long)node * DIMS4 + c];   // self term

    int i = 0;
    for (; i + 4 <= cnt; i += 4) {
        int s0 = g_csr[start + i + 0];
        int s1 = g_csr[start + i + 1];
        int s2 = g_csr[start + i + 2];
        int s3 = g_csr[start + i + 3];
        float4 v0 = x[(long long)s0 * DIMS4 + c];
        float4 v1 = x[(long long)s1 * DIMS4 + c];
        float4 v2 = x[(long long)s2 * DIMS4 + c];
        float4 v3 = x[(long long)s3 * DIMS4 + c];
        acc.x += v0.x + v1.x + v2.x + v3.x;
        acc.y += v0.y + v1.y + v2.y + v3.y;
        acc.z += v0.z + v1.z + v2.z + v3.z;
        acc.w += v0.w + v1.w + v2.w + v3.w;
    }
    for (; i < cnt; i++) {
        int s = g_csr[start + i];
        float4 v = x[(long long)s * DIMS4 + c];
        acc.x += v.x; acc.y += v.y; acc.z += v.z; acc.w += v.w;
    }

    float inv = g_inv[node];
    acc.x *= inv; acc.y *= inv; acc.z *= inv; acc.w *= inv;
    if (BIAS) {
        float4 bb = ((const float4*)bias)[c];
        acc.x += bb.x; acc.y += bb.y; acc.z += bb.z; acc.w += bb.w;
    }
    out[(long long)node * DIMS4 + c] = acc;
}

// ---------------- GEMM: C[M,BN] = A[M,128] @ W[128,BN] (+bias)(+relu) -------
// BM=64, BK=32, 256 threads (16x16), per-thread tile 4 x (BN/16).
template <int BN, bool RELU, bool BIAS>
__global__ void __launch_bounds__(256)
k_gemm(const float* __restrict__ A, const float* __restrict__ W,
       const float* __restrict__ bias, float* __restrict__ C) {
    constexpr int K  = 128;
    constexpr int BM = 64;
    constexpr int BK = 32;
    constexpr int TN = BN / 16;          // 8 (BN=128) or 4 (BN=64)

    __shared__ float As[BM][BK + 1];
    __shared__ float Ws[BK][BN];

    const int tid = threadIdx.x;
    const int tx  = tid & 15;
    const int ty  = tid >> 4;
    const int m0  = blockIdx.x * BM;

    float acc[4][TN];
#pragma unroll
    for (int i = 0; i < 4; i++)
#pragma unroll
        for (int j = 0; j < TN; j++) acc[i][j] = 0.0f;

    for (int k0 = 0; k0 < K; k0 += BK) {
        // load A tile: 64x32 floats = 512 float4, 2 per thread
#pragma unroll
        for (int l = 0; l < 2; l++) {
            int id = tid * 2 + l;
            int r  = id >> 3;
            int c4 = id & 7;
            int m  = m0 + r;
            float4 v = make_float4(0.f, 0.f, 0.f, 0.f);
            if (m < N_NODES)
                v = ((const float4*)(A + (long long)m * K + k0))[c4];
            As[r][c4 * 4 + 0] = v.x;
            As[r][c4 * 4 + 1] = v.y;
            As[r][c4 * 4 + 2] = v.z;
            As[r][c4 * 4 + 3] = v.w;
        }
        // load W tile: 32xBN floats, BN/32 float4 per thread
        constexpr int WF4 = BN / 32;
#pragma unroll
        for (int l = 0; l < WF4; l++) {
            int id = tid * WF4 + l;
            int k  = id / (BN / 4);
            int n4 = id % (BN / 4);
            float4 v = ((const float4*)(W + (long long)(k0 + k) * BN))[n4];
            *((float4*)&Ws[k][n4 * 4]) = v;
        }
        __syncthreads();

#pragma unroll
        for (int kk = 0; kk < BK; kk++) {
            float a[4];
#pragma unroll
            for (int i = 0; i < 4; i++) a[i] = As[ty * 4 + i][kk];
            float b[TN];
#pragma unroll
            for (int j = 0; j < TN; j++) b[j] = Ws[kk][tx * TN + j];
#pragma unroll
            for (int i = 0; i < 4; i++)
#pragma unroll
                for (int j = 0; j < TN; j++)
                    acc[i][j] = fmaf(a[i], b[j], acc[i][j]);
        }
        __syncthreads();
    }

#pragma unroll
    for (int i = 0; i < 4; i++) {
        int m = m0 + ty * 4 + i;
        if (m < N_NODES) {
#pragma unroll
            for (int j = 0; j < TN; j++) {
                int n  = tx * TN + j;
                float v = acc[i][j];
                if (BIAS) v += bias[n];
                if (RELU) v = fmaxf(v, 0.0f);
                C[(long long)m * BN + n] = v;
            }
        }
    }
}

// ---------------- launch ----------------
extern "C" void kernel_launch(void* const* d_in, const int* in_sizes, int n_in,
                              void* d_out, int out_size) {
    const float* feat = (const float*)d_in[0];   // [100000,128]
    const float* W1   = (const float*)d_in[1];   // [128,128]
    const float* b1   = (const float*)d_in[2];   // [128]
    const float* W2   = (const float*)d_in[3];   // [128,64]
    const float* b2   = (const float*)d_in[4];   // [64]
    const int*   src  = (const int*)d_in[5];     // [1600000]
    const int*   dst  = (const int*)d_in[6];     // [1600000]
    float*       out  = (float*)d_out;           // [100000,64]

    void *p_hn, *p_h1, *p_y2;
    cudaGetSymbolAddress(&p_hn, g_hn);
    cudaGetSymbolAddress(&p_h1, g_h1);
    cudaGetSymbolAddress(&p_y2, g_y2);
    float* hn = (float*)p_hn;
    float* h1 = (float*)p_h1;
    float* y2 = (float*)p_y2;

    // CSR build (reused by both layers)
    k_zero_cnt<<<(N_NODES + 255) / 256, 256>>>();
    k_hist<<<(N_EDGES + 255) / 256, 256>>>(dst);
    k_scan<<<1, 1024>>>();
    k_fill<<<(N_EDGES + 255) / 256, 256>>>(src, dst);

    // layer 1: aggregate feat (128 dims) -> hn = (agg+self)*inv
    {
        long long th = (long long)N_NODES * 32;
        k_agg<32, false><<<(unsigned)((th + 255) / 256), 256>>>(
            (const float4*)feat, nullptr, (float4*)hn);
    }
    // h1 = relu(hn @ W1 + b1)
    k_gemm<128, true, true><<<(N_NODES + 63) / 64, 256>>>(hn, W1, b1, h1);

    // layer 2 (GEMM first, aggregate 64 dims): y2 = h1 @ W2
    k_gemm<64, false, false><<<(N_NODES + 63) / 64, 256>>>(h1, W2, nullptr, y2);

    // out = (agg(y2)+y2)*inv + b2
    {
        long long th = (long long)N_NODES * 16;
        k_agg<16, true><<<(unsigned)((th + 255) / 256), 256>>>(
            (const float4*)y2, b2, (float4*)out);
    }
}

// round 2
// speedup vs baseline: 1.2684x; 1.2684x over previous
#include <cuda_runtime.h>
#include <cuda_bf16.h>
#include <cstdint>

#define N_NODES 100000
#define N_EDGES 1600000
// dims: IN=128, HIDDEN=128, OUT=64

// ---------------- scratch (device globals: allocation-free) ----------------
__device__ int   g_cnt[N_NODES];
__device__ int   g_off[N_NODES];
__device__ int   g_pos[N_NODES];
__device__ float g_inv[N_NODES];
__device__ int   g_csr[N_EDGES];
__device__ float g_hn [N_NODES * 128];   // layer1 aggregated (pre-GEMM1)
__device__ float g_h1 [N_NODES * 128];   // relu(GEMM1)
__device__ float g_y2 [N_NODES * 64];    // GEMM2 output (pre-aggregation)
__device__ __nv_bfloat16 g_W1h[128 * 128];
__device__ __nv_bfloat16 g_W1l[128 * 128];
__device__ __nv_bfloat16 g_W2h[128 * 64];
__device__ __nv_bfloat16 g_W2l[128 * 64];

// ---------------- CSR build ----------------
__global__ void k_zero_cnt() {
    int i = blockIdx.x * blockDim.x + threadIdx.x;
    if (i < N_NODES) g_cnt[i] = 0;
}

__global__ void k_hist(const int* __restrict__ dst) {
    int e = blockIdx.x * blockDim.x + threadIdx.x;
    if (e < N_EDGES) atomicAdd(&g_cnt[dst[e]], 1);
}

// single-block exclusive scan of g_cnt -> g_off (+ g_pos copy, g_inv)
__global__ void k_scan() {
    __shared__ int sh[1024];
    const int t = threadIdx.x;
    const int CH = (N_NODES + 1023) / 1024;   // 98
    const int base = t * CH;
    int s = 0;
    for (int i = 0; i < CH; i++) {
        int idx = base + i;
        if (idx < N_NODES) s += g_cnt[idx];
    }
    sh[t] = s;
    __syncthreads();
    for (int off = 1; off < 1024; off <<= 1) {
        int v = 0;
        if (t >= off) v = sh[t - off];
        __syncthreads();
        sh[t] += v;
        __syncthreads();
    }
    int run = (t == 0) ? 0 : sh[t - 1];
    for (int i = 0; i < CH; i++) {
        int idx = base + i;
        if (idx < N_NODES) {
            g_off[idx] = run;
            g_pos[idx] = run;
            int c = g_cnt[idx];
            g_inv[idx] = 1.0f / (float)(c + 1);
            run += c;
        }
    }
}

__global__ void k_fill(const int* __restrict__ src, const int* __restrict__ dst) {
    int e = blockIdx.x * blockDim.x + threadIdx.x;
    if (e < N_EDGES) {
        int p = atomicAdd(&g_pos[dst[e]], 1);
        g_csr[p] = src[e];
    }
}

// ---------------- weight split: W -> bf16 hi + bf16 lo ----------------
__global__ void k_splitW(const float* __restrict__ W,
                         __nv_bfloat16* __restrict__ Wh,
                         __nv_bfloat16* __restrict__ Wl, int n) {
    int i = blockIdx.x * blockDim.x + threadIdx.x;
    if (i < n) {
        float w = W[i];
        __nv_bfloat16 h = __float2bfloat16(w);
        Wh[i] = h;
        Wl[i] = __float2bfloat16(w - __bfloat162float(h));
    }
}

// ---------------- aggregation: out[n] = (sum_{s->n} x[s] + x[n]) * inv[n] (+bias) ----
template <int DIMS4, bool BIAS>
__global__ void k_agg(const float4* __restrict__ x,
                      const float*  __restrict__ bias,
                      float4*       __restrict__ out) {
    long long t = (long long)blockIdx.x * blockDim.x + threadIdx.x;
    int node = (int)(t / DIMS4);
    int c    = (int)(t % DIMS4);
    if (node >= N_NODES) return;

    const int start = g_off[node];
    const int cnt   = g_cnt[node];

    float4 acc = x[(long long)node * DIMS4 + c];   // self term

    int i = 0;
    for (; i + 4 <= cnt; i += 4) {
        int s0 = g_csr[start + i + 0];
        int s1 = g_csr[start + i + 1];
        int s2 = g_csr[start + i + 2];
        int s3 = g_csr[start + i + 3];
        float4 v0 = x[(long long)s0 * DIMS4 + c];
        float4 v1 = x[(long long)s1 * DIMS4 + c];
        float4 v2 = x[(long long)s2 * DIMS4 + c];
        float4 v3 = x[(long long)s3 * DIMS4 + c];
        acc.x += v0.x + v1.x + v2.x + v3.x;
        acc.y += v0.y + v1.y + v2.y + v3.y;
        acc.z += v0.z + v1.z + v2.z + v3.z;
        acc.w += v0.w + v1.w + v2.w + v3.w;
    }
    for (; i < cnt; i++) {
        int s = g_csr[start + i];
        float4 v = x[(long long)s * DIMS4 + c];
        acc.x += v.x; acc.y += v.y; acc.z += v.z; acc.w += v.w;
    }

    float inv = g_inv[node];
    acc.x *= inv; acc.y *= inv; acc.z *= inv; acc.w *= inv;
    if (BIAS) {
        float4 bb = ((const float4*)bias)[c];
        acc.x += bb.x; acc.y += bb.y; acc.z += bb.z; acc.w += bb.w;
    }
    out[(long long)node * DIMS4 + c] = acc;
}

// ---------------- tensor-core GEMM (bf16 split, 3-pass compensated) --------
// C[M,BN] = A[M,128] @ W[128,BN] (+bias)(+relu), fp32 in/out, ~fp32 accuracy.
__device__ __forceinline__ uint32_t smem_u32p(const void* p) {
    return (uint32_t)__cvta_generic_to_shared(p);
}

__device__ __forceinline__ void ldsm_x4(uint32_t* r, uint32_t addr) {
    asm volatile("ldmatrix.sync.aligned.m8n8.x4.shared.b16 {%0,%1,%2,%3}, [%4];"
                 : "=r"(r[0]), "=r"(r[1]), "=r"(r[2]), "=r"(r[3]) : "r"(addr));
}
__device__ __forceinline__ void ldsm_x2t(uint32_t* r, uint32_t addr) {
    asm volatile("ldmatrix.sync.aligned.m8n8.x2.trans.shared.b16 {%0,%1}, [%2];"
                 : "=r"(r[0]), "=r"(r[1]) : "r"(addr));
}
__device__ __forceinline__ void mma_bf16(float* c, const uint32_t* a, const uint32_t* b) {
    asm volatile(
        "mma.sync.aligned.m16n8k16.row.col.f32.bf16.bf16.f32 "
        "{%0,%1,%2,%3}, {%4,%5,%6,%7}, {%8,%9}, {%0,%1,%2,%3};"
        : "+f"(c[0]), "+f"(c[1]), "+f"(c[2]), "+f"(c[3])
        : "r"(a[0]), "r"(a[1]), "r"(a[2]), "r"(a[3]), "r"(b[0]), "r"(b[1]));
}

template <int BN, bool RELU, bool BIAS>
__global__ void __launch_bounds__(256)
k_gemm_tc(const float* __restrict__ A,
          const __nv_bfloat16* __restrict__ Wh,
          const __nv_bfloat16* __restrict__ Wl,
          const float* __restrict__ bias,
          float* __restrict__ C) {
    constexpr int K   = 128;
    constexpr int BM  = 128;
    constexpr int BK  = 32;
    constexpr int BKP = 40;        // +8 halves pad -> 80B row stride (16B-mult, bank-clean)
    constexpr int BNP = BN + 8;    // row stride 272B/144B (16B-mult, bank-clean)
    constexpr int WNT = BN / 2;    // per-warp N extent (warps 4x2)
    constexpr int NT  = WNT / 8;   // 8 (BN=128) or 4 (BN=64)
    constexpr int MT  = 2;         // per-warp M tiles of 16 (warp M extent 32)

    __shared__ __align__(16) __nv_bfloat16 sAh[BM][BKP];
    __shared__ __align__(16) __nv_bfloat16 sAl[BM][BKP];
    __shared__ __align__(16) __nv_bfloat16 sBh[BK][BNP];
    __shared__ __align__(16) __nv_bfloat16 sBl[BK][BNP];

    const int tid  = threadIdx.x;
    const int lane = tid & 31;
    const int wid  = tid >> 5;
    const int wm   = wid & 3;          // 0..3
    const int wn   = wid >> 2;         // 0..1
    const int m0   = blockIdx.x * BM;
    const int warp_m = wm * 32;
    const int warp_n = wn * WNT;

    float c[MT][NT][4];
#pragma unroll
    for (int mt = 0; mt < MT; mt++)
#pragma unroll
        for (int nt = 0; nt < NT; nt++)
#pragma unroll
            for (int j = 0; j < 4; j++) c[mt][nt][j] = 0.0f;

    for (int k0 = 0; k0 < K; k0 += BK) {
        if (k0) __syncthreads();
        // ---- load + split A tile (128 x 32 fp32 -> bf16 hi/lo) ----
        {
            const int r  = tid >> 3;        // 0..31
            const int c4 = tid & 7;         // 0..7 (float4 col)
#pragma unroll
            for (int i = 0; i < 4; i++) {
                int row = r + i * 32;
                int m   = m0 + row;
                float4 v = make_float4(0.f, 0.f, 0.f, 0.f);
                if (m < N_NODES)
                    v = *(const float4*)(A + (size_t)m * K + k0 + c4 * 4);
                float f[4] = {v.x, v.y, v.z, v.w};
#pragma unroll
                for (int j = 0; j < 4; j++) {
                    __nv_bfloat16 h = __float2bfloat16(f[j]);
                    sAh[row][c4 * 4 + j] = h;
                    sAl[row][c4 * 4 + j] = __float2bfloat16(f[j] - __bfloat162float(h));
                }
            }
        }
        // ---- load W tile (pre-split bf16, row-major [K][BN]) ----
        {
            constexpr int PAIRS = BK * BN / 2;
            constexpr int PER   = PAIRS / 256;   // 8 or 4
#pragma unroll
            for (int i = 0; i < PER; i++) {
                int p  = tid + i * 256;
                int k  = p / (BN / 2);
                int n2 = p % (BN / 2);
                uint32_t vh = ((const uint32_t*)Wh)[(size_t)(k0 + k) * (BN / 2) + n2];
                uint32_t vl = ((const uint32_t*)Wl)[(size_t)(k0 + k) * (BN / 2) + n2];
                *(uint32_t*)&sBh[k][n2 * 2] = vh;
                *(uint32_t*)&sBl[k][n2 * 2] = vl;
            }
        }
        __syncthreads();

        // ---- compute ----
#pragma unroll
        for (int kc = 0; kc < BK; kc += 16) {
            uint32_t ah[MT][4], al[MT][4];
#pragma unroll
            for (int mt = 0; mt < MT; mt++) {
                int row = warp_m + mt * 16 + (lane & 15);
                int col = kc + (lane >> 4) * 8;
                ldsm_x4(ah[mt], smem_u32p(&sAh[row][col]));
                ldsm_x4(al[mt], smem_u32p(&sAl[row][col]));
            }
            int krow = kc + (lane & 7) + ((lane >> 3) & 1) * 8;
#pragma unroll
            for (int nt = 0; nt < NT; nt++) {
                int ncol = warp_n + nt * 8;
                uint32_t bh[2], bl[2];
                ldsm_x2t(bh, smem_u32p(&sBh[krow][ncol]));
                ldsm_x2t(bl, smem_u32p(&sBl[krow][ncol]));
#pragma unroll
                for (int mt = 0; mt < MT; mt++) {
                    mma_bf16(c[mt][nt], ah[mt], bh);
                    mma_bf16(c[mt][nt], al[mt], bh);
                    mma_bf16(c[mt][nt], ah[mt], bl);
                }
            }
        }
    }

    // ---- epilogue ----
    const int g = lane >> 2, t = lane & 3;
#pragma unroll
    for (int mt = 0; mt < MT; mt++) {
        int row0 = m0 + warp_m + mt * 16 + g;
        int row1 = row0 + 8;
#pragma unroll
        for (int nt = 0; nt < NT; nt++) {
            int col = warp_n + nt * 8 + t * 2;
            float bx = 0.f, by = 0.f;
            if (BIAS) {
                float2 bb = *(const float2*)(bias + col);
                bx = bb.x; by = bb.y;
            }
            float v0 = c[mt][nt][0] + bx, v1 = c[mt][nt][1] + by;
            float v2 = c[mt][nt][2] + bx, v3 = c[mt][nt][3] + by;
            if (RELU) {
                v0 = fmaxf(v0, 0.f); v1 = fmaxf(v1, 0.f);
                v2 = fmaxf(v2, 0.f); v3 = fmaxf(v3, 0.f);
            }
            if (row0 < N_NODES)
                *(float2*)(C + (size_t)row0 * BN + col) = make_float2(v0, v1);
            if (row1 < N_NODES)
                *(float2*)(C + (size_t)row1 * BN + col) = make_float2(v2, v3);
        }
    }
}

// ---------------- launch ----------------
extern "C" void kernel_launch(void* const* d_in, const int* in_sizes, int n_in,
                              void* d_out, int out_size) {
    const float* feat = (const float*)d_in[0];   // [100000,128]
    const float* W1   = (const float*)d_in[1];   // [128,128]
    const float* b1   = (const float*)d_in[2];   // [128]
    const float* W2   = (const float*)d_in[3];   // [128,64]
    const float* b2   = (const float*)d_in[4];   // [64]
    const int*   src  = (const int*)d_in[5];     // [1600000]
    const int*   dst  = (const int*)d_in[6];     // [1600000]
    float*       out  = (float*)d_out;           // [100000,64]

    void *p_hn, *p_h1, *p_y2, *p_w1h, *p_w1l, *p_w2h, *p_w2l;
    cudaGetSymbolAddress(&p_hn, g_hn);
    cudaGetSymbolAddress(&p_h1, g_h1);
    cudaGetSymbolAddress(&p_y2, g_y2);
    cudaGetSymbolAddress(&p_w1h, g_W1h);
    cudaGetSymbolAddress(&p_w1l, g_W1l);
    cudaGetSymbolAddress(&p_w2h, g_W2h);
    cudaGetSymbolAddress(&p_w2l, g_W2l);
    float* hn = (float*)p_hn;
    float* h1 = (float*)p_h1;
    float* y2 = (float*)p_y2;
    __nv_bfloat16* W1h = (__nv_bfloat16*)p_w1h;
    __nv_bfloat16* W1l = (__nv_bfloat16*)p_w1l;
    __nv_bfloat16* W2h = (__nv_bfloat16*)p_w2h;
    __nv_bfloat16* W2l = (__nv_bfloat16*)p_w2l;

    // CSR build (reused by both layers) + weight split
    k_zero_cnt<<<(N_NODES + 255) / 256, 256>>>();
    k_hist<<<(N_EDGES + 255) / 256, 256>>>(dst);
    k_splitW<<<(128 * 128 + 255) / 256, 256>>>(W1, W1h, W1l, 128 * 128);
    k_splitW<<<(128 * 64 + 255) / 256, 256>>>(W2, W2h, W2l, 128 * 64);
    k_scan<<<1, 1024>>>();
    k_fill<<<(N_EDGES + 255) / 256, 256>>>(src, dst);

    // layer 1: aggregate feat (128 dims) -> hn = (agg+self)*inv
    {
        long long th = (long long)N_NODES * 32;
        k_agg<32, false><<<(unsigned)((th + 255) / 256), 256>>>(
            (const float4*)feat, nullptr, (float4*)hn);
    }
    // h1 = relu(hn @ W1 + b1)
    k_gemm_tc<128, true, true><<<(N_NODES + 127) / 128, 256>>>(hn, W1h, W1l, b1, h1);

    // layer 2 (GEMM first, aggregate 64 dims): y2 = h1 @ W2
    k_gemm_tc<64, false, false><<<(N_NODES + 127) / 128, 256>>>(h1, W2h, W2l, nullptr, y2);

    // out = (agg(y2)+y2)*inv + b2
    {
        long long th = (long long)N_NODES * 16;
        k_agg<16, true><<<(unsigned)((th + 255) / 256), 256>>>(
            (const float4*)y2, b2, (float4*)out);
    }
}

// round 5
// speedup vs baseline: 1.2978x; 1.0231x over previous
#include <cuda_runtime.h>
#include <cuda_bf16.h>
#include <cstdint>

#define N_NODES 100000
#define N_EDGES 1600000
// dims: IN=128, HIDDEN=128, OUT=64

// ---------------- scratch (device globals: allocation-free) ----------------
__device__ int   g_cnt[N_NODES];
__device__ int   g_off[N_NODES];
__device__ int   g_pos[N_NODES];
__device__ float g_inv[N_NODES];
__device__ int   g_csr[N_EDGES];
__device__ float g_hn [N_NODES * 128];   // layer1 aggregated (pre-GEMM1)
__device__ float g_h1 [N_NODES * 128];   // relu(GEMM1)
__device__ float g_y2 [N_NODES * 64];    // GEMM2 output (pre-aggregation)
__device__ __nv_bfloat16 g_W1h[128 * 128];
__device__ __nv_bfloat16 g_W1l[128 * 128];
__device__ __nv_bfloat16 g_W2h[128 * 64];
__device__ __nv_bfloat16 g_W2l[128 * 64];

// ---------------- CSR build ----------------
__global__ void k_zero_cnt() {
    int i = blockIdx.x * blockDim.x + threadIdx.x;
    if (i < N_NODES) g_cnt[i] = 0;
}

__global__ void k_hist(const int* __restrict__ dst) {
    int e = blockIdx.x * blockDim.x + threadIdx.x;
    if (e < N_EDGES) atomicAdd(&g_cnt[dst[e]], 1);
}

// split BOTH weight matrices in one launch (keeps launch count stable for ncu)
__global__ void k_splitW_all(const float* __restrict__ W1,
                             const float* __restrict__ W2,
                             __nv_bfloat16* __restrict__ W1h,
                             __nv_bfloat16* __restrict__ W1l,
                             __nv_bfloat16* __restrict__ W2h,
                             __nv_bfloat16* __restrict__ W2l) {
    int i = blockIdx.x * blockDim.x + threadIdx.x;
    const int N1 = 128 * 128, N2 = 128 * 64;
    if (i < N1) {
        float w = W1[i];
        __nv_bfloat16 h = __float2bfloat16(w);
        W1h[i] = h;
        W1l[i] = __float2bfloat16(w - __bfloat162float(h));
    } else if (i < N1 + N2) {
        int j = i - N1;
        float w = W2[j];
        __nv_bfloat16 h = __float2bfloat16(w);
        W2h[j] = h;
        W2l[j] = __float2bfloat16(w - __bfloat162float(h));
    }
}

// single-block exclusive scan of g_cnt -> g_off (+ g_pos copy, g_inv)
__global__ void k_scan() {
    __shared__ int sh[1024];
    const int t = threadIdx.x;
    const int CH = (N_NODES + 1023) / 1024;   // 98
    const int base = t * CH;
    int s = 0;
    for (int i = 0; i < CH; i++) {
        int idx = base + i;
        if (idx < N_NODES) s += g_cnt[idx];
    }
    sh[t] = s;
    __syncthreads();
    for (int off = 1; off < 1024; off <<= 1) {
        int v = 0;
        if (t >= off) v = sh[t - off];
        __syncthreads();
        sh[t] += v;
        __syncthreads();
    }
    int run = (t == 0) ? 0 : sh[t - 1];
    for (int i = 0; i < CH; i++) {
        int idx = base + i;
        if (idx < N_NODES) {
            g_off[idx] = run;
            g_pos[idx] = run;
            int c = g_cnt[idx];
            g_inv[idx] = 1.0f / (float)(c + 1);
            run += c;
        }
    }
}

__global__ void k_fill(const int* __restrict__ src, const int* __restrict__ dst) {
    int e = blockIdx.x * blockDim.x + threadIdx.x;
    if (e < N_EDGES) {
        int p = atomicAdd(&g_pos[dst[e]], 1);
        g_csr[p] = src[e];
    }
}

// ---------------- aggregation (warp per node, shfl-distributed indices) ----
// out[n] = (sum_{s->n} x[s] + x[n]) * inv[n]            (128 dims, float4 lanes)
__global__ void __launch_bounds__(256)
k_agg128(const float4* __restrict__ x, float4* __restrict__ out) {
    const int warp = (blockIdx.x * blockDim.x + threadIdx.x) >> 5;
    const int lane = threadIdx.x & 31;
    if (warp >= N_NODES) return;

    const int start = g_off[warp];
    const int cnt   = g_cnt[warp];

    float4 acc = x[(size_t)warp * 32 + lane];   // self term

    for (int i0 = 0; i0 < cnt; i0 += 32) {
        const int nb = min(32, cnt - i0);
        int idx = 0;
        if (lane < nb) idx = g_csr[start + i0 + lane];

        int j = 0;
        for (; j + 8 <= nb; j += 8) {
            int s[8];
#pragma unroll
            for (int k = 0; k < 8; k++) s[k] = __shfl_sync(0xffffffffu, idx, j + k);
            float4 v[8];
#pragma unroll
            for (int k = 0; k < 8; k++) v[k] = x[(size_t)s[k] * 32 + lane];
#pragma unroll
            for (int k = 0; k < 8; k++) {
                acc.x += v[k].x; acc.y += v[k].y; acc.z += v[k].z; acc.w += v[k].w;
            }
        }
        for (; j < nb; j++) {
            int s = __shfl_sync(0xffffffffu, idx, j);
            float4 v = x[(size_t)s * 32 + lane];
            acc.x += v.x; acc.y += v.y; acc.z += v.z; acc.w += v.w;
        }
    }

    const float inv = g_inv[warp];
    acc.x *= inv; acc.y *= inv; acc.z *= inv; acc.w *= inv;
    __stcs(&out[(size_t)warp * 32 + lane], acc);
}

// out[n] = (sum x[s] + x[n]) * inv[n] + bias            (64 dims, float2 lanes)
__global__ void __launch_bounds__(256)
k_agg64(const float2* __restrict__ x, const float* __restrict__ bias,
        float2* __restrict__ out) {
    const int warp = (blockIdx.x * blockDim.x + threadIdx.x) >> 5;
    const int lane = threadIdx.x & 31;
    if (warp >= N_NODES) return;

    const int start = g_off[warp];
    const int cnt   = g_cnt[warp];

    float2 acc = x[(size_t)warp * 32 + lane];   // self term

    for (int i0 = 0; i0 < cnt; i0 += 32) {
        const int nb = min(32, cnt - i0);
        int idx = 0;
        if (lane < nb) idx = g_csr[start + i0 + lane];

        int j = 0;
        for (; j + 8 <= nb; j += 8) {
            int s[8];
#pragma unroll
            for (int k = 0; k < 8; k++) s[k] = __shfl_sync(0xffffffffu, idx, j + k);
            float2 v[8];
#pragma unroll
            for (int k = 0; k < 8; k++) v[k] = x[(size_t)s[k] * 32 + lane];
#pragma unroll
            for (int k = 0; k < 8; k++) { acc.x += v[k].x; acc.y += v[k].y; }
        }
        for (; j < nb; j++) {
            int s = __shfl_sync(0xffffffffu, idx, j);
            float2 v = x[(size_t)s * 32 + lane];
            acc.x += v.x; acc.y += v.y;
        }
    }

    const float inv = g_inv[warp];
    float2 bb = ((const float2*)bias)[lane];
    acc.x = acc.x * inv + bb.x;
    acc.y = acc.y * inv + bb.y;
    __stcs(&out[(size_t)warp * 32 + lane], acc);
}

// ---------------- tensor-core GEMM (bf16 split, 3-pass compensated) --------
__device__ __forceinline__ uint32_t smem_u32p(const void* p) {
    return (uint32_t)__cvta_generic_to_shared(p);
}

__device__ __forceinline__ void ldsm_x4(uint32_t* r, uint32_t addr) {
    asm volatile("ldmatrix.sync.aligned.m8n8.x4.shared.b16 {%0,%1,%2,%3}, [%4];"
                 : "=r"(r[0]), "=r"(r[1]), "=r"(r[2]), "=r"(r[3]) : "r"(addr));
}
__device__ __forceinline__ void ldsm_x2t(uint32_t* r, uint32_t addr) {
    asm volatile("ldmatrix.sync.aligned.m8n8.x2.trans.shared.b16 {%0,%1}, [%2];"
                 : "=r"(r[0]), "=r"(r[1]) : "r"(addr));
}
__device__ __forceinline__ void mma_bf16(float* c, const uint32_t* a, const uint32_t* b) {
    asm volatile(
        "mma.sync.aligned.m16n8k16.row.col.f32.bf16.bf16.f32 "
        "{%0,%1,%2,%3}, {%4,%5,%6,%7}, {%8,%9}, {%0,%1,%2,%3};"
        : "+f"(c[0]), "+f"(c[1]), "+f"(c[2]), "+f"(c[3])
        : "r"(a[0]), "r"(a[1]), "r"(a[2]), "r"(a[3]), "r"(b[0]), "r"(b[1]));
}

template <int BN, bool RELU, bool BIAS>
__global__ void __launch_bounds__(256)
k_gemm_tc(const float* __restrict__ A,
          const __nv_bfloat16* __restrict__ Wh,
          const __nv_bfloat16* __restrict__ Wl,
          const float* __restrict__ bias,
          float* __restrict__ C) {
    constexpr int K   = 128;
    constexpr int BM  = 128;
    constexpr int BK  = 32;
    constexpr int BKP = 40;
    constexpr int BNP = BN + 8;
    constexpr int WNT = BN / 2;
    constexpr int NT  = WNT / 8;
    constexpr int MT  = 2;

    __shared__ __align__(16) __nv_bfloat16 sAh[BM][BKP];
    __shared__ __align__(16) __nv_bfloat16 sAl[BM][BKP];
    __shared__ __align__(16) __nv_bfloat16 sBh[BK][BNP];
    __shared__ __align__(16) __nv_bfloat16 sBl[BK][BNP];

    const int tid  = threadIdx.x;
    const int lane = tid & 31;
    const int wid  = tid >> 5;
    const int wm   = wid & 3;
    const int wn   = wid >> 2;
    const int m0   = blockIdx.x * BM;
    const int warp_m = wm * 32;
    const int warp_n = wn * WNT;

    float c[MT][NT][4];
#pragma unroll
    for (int mt = 0; mt < MT; mt++)
#pragma unroll
        for (int nt = 0; nt < NT; nt++)
#pragma unroll
            for (int j = 0; j < 4; j++) c[mt][nt][j] = 0.0f;

    for (int k0 = 0; k0 < K; k0 += BK) {
        if (k0) __syncthreads();
        // ---- load + split A tile (streaming: evict-first) ----
        {
            const int r  = tid >> 3;
            const int c4 = tid & 7;
#pragma unroll
            for (int i = 0; i < 4; i++) {
                int row = r + i * 32;
                int m   = m0 + row;
                float4 v = make_float4(0.f, 0.f, 0.f, 0.f);
                if (m < N_NODES)
                    v = __ldcs((const float4*)(A + (size_t)m * K + k0 + c4 * 4));
                float f[4] = {v.x, v.y, v.z, v.w};
#pragma unroll
                for (int j = 0; j < 4; j++) {
                    __nv_bfloat16 h = __float2bfloat16(f[j]);
                    sAh[row][c4 * 4 + j] = h;
                    sAl[row][c4 * 4 + j] = __float2bfloat16(f[j] - __bfloat162float(h));
                }
            }
        }
        // ---- load W tile (pre-split bf16, row-major [K][BN]) ----
        {
            constexpr int PAIRS = BK * BN / 2;
            constexpr int PER   = PAIRS / 256;
#pragma unroll
            for (int i = 0; i < PER; i++) {
                int p  = tid + i * 256;
                int k  = p / (BN / 2);
                int n2 = p % (BN / 2);
                uint32_t vh = ((const uint32_t*)Wh)[(size_t)(k0 + k) * (BN / 2) + n2];
                uint32_t vl = ((const uint32_t*)Wl)[(size_t)(k0 + k) * (BN / 2) + n2];
                *(uint32_t*)&sBh[k][n2 * 2] = vh;
                *(uint32_t*)&sBl[k][n2 * 2] = vl;
            }
        }
        __syncthreads();

#pragma unroll
        for (int kc = 0; kc < BK; kc += 16) {
            uint32_t ah[MT][4], al[MT][4];
#pragma unroll
            for (int mt = 0; mt < MT; mt++) {
                int row = warp_m + mt * 16 + (lane & 15);
                int col = kc + (lane >> 4) * 8;
                ldsm_x4(ah[mt], smem_u32p(&sAh[row][col]));
                ldsm_x4(al[mt], smem_u32p(&sAl[row][col]));
            }
            int krow = kc + (lane & 7) + ((lane >> 3) & 1) * 8;
#pragma unroll
            for (int nt = 0; nt < NT; nt++) {
                int ncol = warp_n + nt * 8;
                uint32_t bh[2], bl[2];
                ldsm_x2t(bh, smem_u32p(&sBh[krow][ncol]));
                ldsm_x2t(bl, smem_u32p(&sBl[krow][ncol]));
#pragma unroll
                for (int mt = 0; mt < MT; mt++) {
                    mma_bf16(c[mt][nt], ah[mt], bh);
                    mma_bf16(c[mt][nt], al[mt], bh);
                    mma_bf16(c[mt][nt], ah[mt], bl);
                }
            }
        }
    }

    const int g = lane >> 2, t = lane & 3;
#pragma unroll
    for (int mt = 0; mt < MT; mt++) {
        int row0 = m0 + warp_m + mt * 16 + g;
        int row1 = row0 + 8;
#pragma unroll
        for (int nt = 0; nt < NT; nt++) {
            int col = warp_n + nt * 8 + t * 2;
            float bx = 0.f, by = 0.f;
            if (BIAS) {
                float2 bb = *(const float2*)(bias + col);
                bx = bb.x; by = bb.y;
            }
            float v0 = c[mt][nt][0] + bx, v1 = c[mt][nt][1] + by;
            float v2 = c[mt][nt][2] + bx, v3 = c[mt][nt][3] + by;
            if (RELU) {
                v0 = fmaxf(v0, 0.f); v1 = fmaxf(v1, 0.f);
                v2 = fmaxf(v2, 0.f); v3 = fmaxf(v3, 0.f);
            }
            if (row0 < N_NODES)
                *(float2*)(C + (size_t)row0 * BN + col) = make_float2(v0, v1);
            if (row1 < N_NODES)
                *(float2*)(C + (size_t)row1 * BN + col) = make_float2(v2, v3);
        }
    }
}

// ---------------- launch ----------------
extern "C" void kernel_launch(void* const* d_in, const int* in_sizes, int n_in,
                              void* d_out, int out_size) {
    const float* feat = (const float*)d_in[0];
    const float* W1   = (const float*)d_in[1];
    const float* b1   = (const float*)d_in[2];
    const float* W2   = (const float*)d_in[3];
    const float* b2   = (const float*)d_in[4];
    const int*   src  = (const int*)d_in[5];
    const int*   dst  = (const int*)d_in[6];
    float*       out  = (float*)d_out;

    void *p_hn, *p_h1, *p_y2, *p_w1h, *p_w1l, *p_w2h, *p_w2l;
    cudaGetSymbolAddress(&p_hn, g_hn);
    cudaGetSymbolAddress(&p_h1, g_h1);
    cudaGetSymbolAddress(&p_y2, g_y2);
    cudaGetSymbolAddress(&p_w1h, g_W1h);
    cudaGetSymbolAddress(&p_w1l, g_W1l);
    cudaGetSymbolAddress(&p_w2h, g_W2h);
    cudaGetSymbolAddress(&p_w2l, g_W2l);
    float* hn = (float*)p_hn;
    float* h1 = (float*)p_h1;
    float* y2 = (float*)p_y2;

    // launches 1..5 (so ncu -s 5 -c 1 profiles k_agg128)
    k_zero_cnt<<<(N_NODES + 255) / 256, 256>>>();
    k_hist<<<(N_EDGES + 255) / 256, 256>>>(dst);
    k_splitW_all<<<(128 * 128 + 128 * 64 + 255) / 256, 256>>>(
        W1, W2, (__nv_bfloat16*)p_w1h, (__nv_bfloat16*)p_w1l,
        (__nv_bfloat16*)p_w2h, (__nv_bfloat16*)p_w2l);
    k_scan<<<1, 1024>>>();
    k_fill<<<(N_EDGES + 255) / 256, 256>>>(src, dst);

    // layer 1: aggregate feat (128 dims) -> hn
    k_agg128<<<(N_NODES * 32 + 255) / 256, 256>>>((const float4*)feat, (float4*)hn);
    // h1 = relu(hn @ W1 + b1)
    k_gemm_tc<128, true, true><<<(N_NODES + 127) / 128, 256>>>(
        hn, (__nv_bfloat16*)p_w1h, (__nv_bfloat16*)p_w1l, b1, h1);
    // layer 2 (GEMM first): y2 = h1 @ W2
    k_gemm_tc<64, false, false><<<(N_NODES + 127) / 128, 256>>>(
        h1, (__nv_bfloat16*)p_w2h, (__nv_bfloat16*)p_w2l, nullptr, y2);
    // out = (agg(y2)+y2)*inv + b2
    k_agg64<<<(N_NODES * 32 + 255) / 256, 256>>>((const float2*)y2, b2, (float2*)out);
}

// round 6
// speedup vs baseline: 2.4679x; 1.9016x over previous
#include <cuda_runtime.h>
#include <cuda_bf16.h>
#include <cstdint>

#define N_NODES 100000
#define N_EDGES 1600000
// dims: IN=128, HIDDEN=128, OUT=64

#define SCAN_B 1024
#define SCAN_G ((N_NODES + SCAN_B - 1) / SCAN_B)   // 98

// ---------------- scratch (device globals: allocation-free) ----------------
__device__ int   g_cnt[N_NODES];
__device__ int   g_off[N_NODES];
__device__ int   g_pos[N_NODES];
__device__ float g_inv[N_NODES];
__device__ int   g_blk[SCAN_G];
__device__ int   g_csr[N_EDGES];
__device__ float g_hn [N_NODES * 128];   // layer1 aggregated (pre-GEMM1)
__device__ float g_h1 [N_NODES * 128];   // relu(GEMM1)
__device__ float g_y2 [N_NODES * 64];    // GEMM2 output (pre-aggregation)
__device__ __nv_bfloat16 g_W1h[128 * 128];
__device__ __nv_bfloat16 g_W1l[128 * 128];
__device__ __nv_bfloat16 g_W2h[128 * 64];
__device__ __nv_bfloat16 g_W2l[128 * 64];

// ---------------- init: zero counts + split both weight matrices ----------
__global__ void k_init(const float* __restrict__ W1,
                       const float* __restrict__ W2,
                       __nv_bfloat16* __restrict__ W1h,
                       __nv_bfloat16* __restrict__ W1l,
                       __nv_bfloat16* __restrict__ W2h,
                       __nv_bfloat16* __restrict__ W2l) {
    int i = blockIdx.x * blockDim.x + threadIdx.x;
    if (i < N_NODES) g_cnt[i] = 0;
    if (i < 128 * 128) {
        float w = W1[i];
        __nv_bfloat16 h = __float2bfloat16(w);
        W1h[i] = h;
        W1l[i] = __float2bfloat16(w - __bfloat162float(h));
    }
    if (i < 128 * 64) {
        float w = W2[i];
        __nv_bfloat16 h = __float2bfloat16(w);
        W2h[i] = h;
        W2l[i] = __float2bfloat16(w - __bfloat162float(h));
    }
}

__global__ void k_hist(const int* __restrict__ dst) {
    int e = blockIdx.x * blockDim.x + threadIdx.x;
    if (e < N_EDGES) atomicAdd(&g_cnt[dst[e]], 1);
}

// ---------------- parallel scan phase 1: block sums ----------------
__global__ void __launch_bounds__(SCAN_B)
k_s1() {
    __shared__ int sw[32];
    const int t = threadIdx.x;
    const int i = blockIdx.x * SCAN_B + t;
    int v = (i < N_NODES) ? g_cnt[i] : 0;
    // warp reduce
    int s = v;
#pragma unroll
    for (int o = 16; o > 0; o >>= 1) s += __shfl_down_sync(0xffffffffu, s, o);
    if ((t & 31) == 0) sw[t >> 5] = s;
    __syncthreads();
    if (t < 32) {
        int x = sw[t];
#pragma unroll
        for (int o = 16; o > 0; o >>= 1) x += __shfl_down_sync(0xffffffffu, x, o);
        if (t == 0) g_blk[blockIdx.x] = x;
    }
}

// ---------------- parallel scan phase 2: block prefix + local scan + apply --
__global__ void __launch_bounds__(SCAN_B)
k_s3() {
    __shared__ int sw[32];
    __shared__ int s_pref;
    __shared__ int s_blk[128];
    const int t = threadIdx.x;
    const int b = blockIdx.x;
    const int i = b * SCAN_B + t;

    // block prefix: sum of g_blk[j] for j < b (98 values, smem reduce over 128)
    if (t < 128) s_blk[t] = (t < b) ? g_blk[t] : 0;   // b <= 97 < 128
    __syncthreads();
    if (t < 64) s_blk[t] += s_blk[t + 64];
    __syncthreads();
    if (t < 32) {
        int x = s_blk[t] + s_blk[t + 32];
#pragma unroll
        for (int o = 16; o > 0; o >>= 1) x += __shfl_down_sync(0xffffffffu, x, o);
        if (t == 0) s_pref = x;
    }
    __syncthreads();

    // local exclusive scan of this block's 1024 counts
    int v = (i < N_NODES) ? g_cnt[i] : 0;
    int incl = v;
#pragma unroll
    for (int o = 1; o < 32; o <<= 1) {
        int y = __shfl_up_sync(0xffffffffu, incl, o);
        if ((t & 31) >= o) incl += y;
    }
    if ((t & 31) == 31) sw[t >> 5] = incl;
    __syncthreads();
    if (t < 32) {
        int x = sw[t];
        int xi = x;
#pragma unroll
        for (int o = 1; o < 32; o <<= 1) {
            int y = __shfl_up_sync(0xffffffffu, xi, o);
            if (t >= o) xi += y;
        }
        sw[t] = xi - x;   // exclusive warp offsets
    }
    __syncthreads();

    if (i < N_NODES) {
        int excl = incl - v + sw[t >> 5] + s_pref;
        g_off[i] = excl;
        g_pos[i] = excl;
        g_inv[i] = 1.0f / (float)(v + 1);
    }
}

__global__ void k_fill(const int* __restrict__ src, const int* __restrict__ dst) {
    int e = blockIdx.x * blockDim.x + threadIdx.x;
    if (e < N_EDGES) {
        int p = atomicAdd(&g_pos[dst[e]], 1);
        g_csr[p] = src[e];
    }
}

// ---------------- aggregation (warp per node, shfl-distributed indices) ----
__global__ void __launch_bounds__(256)
k_agg128(const float4* __restrict__ x, float4* __restrict__ out) {
    const int warp = (blockIdx.x * blockDim.x + threadIdx.x) >> 5;
    const int lane = threadIdx.x & 31;
    if (warp >= N_NODES) return;

    const int start = g_off[warp];
    const int cnt   = g_cnt[warp];

    float4 acc = x[(size_t)warp * 32 + lane];   // self term

    for (int i0 = 0; i0 < cnt; i0 += 32) {
        const int nb = min(32, cnt - i0);
        int idx = 0;
        if (lane < nb) idx = g_csr[start + i0 + lane];

        int j = 0;
        for (; j + 8 <= nb; j += 8) {
            int s[8];
#pragma unroll
            for (int k = 0; k < 8; k++) s[k] = __shfl_sync(0xffffffffu, idx, j + k);
            float4 v[8];
#pragma unroll
            for (int k = 0; k < 8; k++) v[k] = x[(size_t)s[k] * 32 + lane];
#pragma unroll
            for (int k = 0; k < 8; k++) {
                acc.x += v[k].x; acc.y += v[k].y; acc.z += v[k].z; acc.w += v[k].w;
            }
        }
        for (; j < nb; j++) {
            int s = __shfl_sync(0xffffffffu, idx, j);
            float4 v = x[(size_t)s * 32 + lane];
            acc.x += v.x; acc.y += v.y; acc.z += v.z; acc.w += v.w;
        }
    }

    const float inv = g_inv[warp];
    acc.x *= inv; acc.y *= inv; acc.z *= inv; acc.w *= inv;
    __stcs(&out[(size_t)warp * 32 + lane], acc);
}

__global__ void __launch_bounds__(256)
k_agg64(const float2* __restrict__ x, const float* __restrict__ bias,
        float2* __restrict__ out) {
    const int warp = (blockIdx.x * blockDim.x + threadIdx.x) >> 5;
    const int lane = threadIdx.x & 31;
    if (warp >= N_NODES) return;

    const int start = g_off[warp];
    const int cnt   = g_cnt[warp];

    float2 acc = x[(size_t)warp * 32 + lane];   // self term

    for (int i0 = 0; i0 < cnt; i0 += 32) {
        const int nb = min(32, cnt - i0);
        int idx = 0;
        if (lane < nb) idx = g_csr[start + i0 + lane];

        int j = 0;
        for (; j + 8 <= nb; j += 8) {
            int s[8];
#pragma unroll
            for (int k = 0; k < 8; k++) s[k] = __shfl_sync(0xffffffffu, idx, j + k);
            float2 v[8];
#pragma unroll
            for (int k = 0; k < 8; k++) v[k] = x[(size_t)s[k] * 32 + lane];
#pragma unroll
            for (int k = 0; k < 8; k++) { acc.x += v[k].x; acc.y += v[k].y; }
        }
        for (; j < nb; j++) {
            int s = __shfl_sync(0xffffffffu, idx, j);
            float2 v = x[(size_t)s * 32 + lane];
            acc.x += v.x; acc.y += v.y;
        }
    }

    const float inv = g_inv[warp];
    float2 bb = ((const float2*)bias)[lane];
    acc.x = acc.x * inv + bb.x;
    acc.y = acc.y * inv + bb.y;
    __stcs(&out[(size_t)warp * 32 + lane], acc);
}

// ---------------- tensor-core GEMM (bf16 split, 3-pass compensated) --------
__device__ __forceinline__ uint32_t smem_u32p(const void* p) {
    return (uint32_t)__cvta_generic_to_shared(p);
}

__device__ __forceinline__ void ldsm_x4(uint32_t* r, uint32_t addr) {
    asm volatile("ldmatrix.sync.aligned.m8n8.x4.shared.b16 {%0,%1,%2,%3}, [%4];"
                 : "=r"(r[0]), "=r"(r[1]), "=r"(r[2]), "=r"(r[3]) : "r"(addr));
}
__device__ __forceinline__ void ldsm_x2t(uint32_t* r, uint32_t addr) {
    asm volatile("ldmatrix.sync.aligned.m8n8.x2.trans.shared.b16 {%0,%1}, [%2];"
                 : "=r"(r[0]), "=r"(r[1]) : "r"(addr));
}
__device__ __forceinline__ void mma_bf16(float* c, const uint32_t* a, const uint32_t* b) {
    asm volatile(
        "mma.sync.aligned.m16n8k16.row.col.f32.bf16.bf16.f32 "
        "{%0,%1,%2,%3}, {%4,%5,%6,%7}, {%8,%9}, {%0,%1,%2,%3};"
        : "+f"(c[0]), "+f"(c[1]), "+f"(c[2]), "+f"(c[3])
        : "r"(a[0]), "r"(a[1]), "r"(a[2]), "r"(a[3]), "r"(b[0]), "r"(b[1]));
}

template <int BN, bool RELU, bool BIAS>
__global__ void __launch_bounds__(256)
k_gemm_tc(const float* __restrict__ A,
          const __nv_bfloat16* __restrict__ Wh,
          const __nv_bfloat16* __restrict__ Wl,
          const float* __restrict__ bias,
          float* __restrict__ C) {
    constexpr int K   = 128;
    constexpr int BM  = 128;
    constexpr int BK  = 32;
    constexpr int BKP = 40;
    constexpr int BNP = BN + 8;
    constexpr int WNT = BN / 2;
    constexpr int NT  = WNT / 8;
    constexpr int MT  = 2;

    __shared__ __align__(16) __nv_bfloat16 sAh[BM][BKP];
    __shared__ __align__(16) __nv_bfloat16 sAl[BM][BKP];
    __shared__ __align__(16) __nv_bfloat16 sBh[BK][BNP];
    __shared__ __align__(16) __nv_bfloat16 sBl[BK][BNP];

    const int tid  = threadIdx.x;
    const int lane = tid & 31;
    const int wid  = tid >> 5;
    const int wm   = wid & 3;
    const int wn   = wid >> 2;
    const int m0   = blockIdx.x * BM;
    const int warp_m = wm * 32;
    const int warp_n = wn * WNT;

    float c[MT][NT][4];
#pragma unroll
    for (int mt = 0; mt < MT; mt++)
#pragma unroll
        for (int nt = 0; nt < NT; nt++)
#pragma unroll
            for (int j = 0; j < 4; j++) c[mt][nt][j] = 0.0f;

    for (int k0 = 0; k0 < K; k0 += BK) {
        if (k0) __syncthreads();
        // ---- load + split A tile (streaming: evict-first) ----
        {
            const int r  = tid >> 3;
            const int c4 = tid & 7;
#pragma unroll
            for (int i = 0; i < 4; i++) {
                int row = r + i * 32;
                int m   = m0 + row;
                float4 v = make_float4(0.f, 0.f, 0.f, 0.f);
                if (m < N_NODES)
                    v = __ldcs((const float4*)(A + (size_t)m * K + k0 + c4 * 4));
                float f[4] = {v.x, v.y, v.z, v.w};
#pragma unroll
                for (int j = 0; j < 4; j++) {
                    __nv_bfloat16 h = __float2bfloat16(f[j]);
                    sAh[row][c4 * 4 + j] = h;
                    sAl[row][c4 * 4 + j] = __float2bfloat16(f[j] - __bfloat162float(h));
                }
            }
        }
        // ---- load W tile (pre-split bf16, row-major [K][BN]) ----
        {
            constexpr int PAIRS = BK * BN / 2;
            constexpr int PER   = PAIRS / 256;
#pragma unroll
            for (int i = 0; i < PER; i++) {
                int p  = tid + i * 256;
                int k  = p / (BN / 2);
                int n2 = p % (BN / 2);
                uint32_t vh = ((const uint32_t*)Wh)[(size_t)(k0 + k) * (BN / 2) + n2];
                uint32_t vl = ((const uint32_t*)Wl)[(size_t)(k0 + k) * (BN / 2) + n2];
                *(uint32_t*)&sBh[k][n2 * 2] = vh;
                *(uint32_t*)&sBl[k][n2 * 2] = vl;
            }
        }
        __syncthreads();

#pragma unroll
        for (int kc = 0; kc < BK; kc += 16) {
            uint32_t ah[MT][4], al[MT][4];
#pragma unroll
            for (int mt = 0; mt < MT; mt++) {
                int row = warp_m + mt * 16 + (lane & 15);
                int col = kc + (lane >> 4) * 8;
                ldsm_x4(ah[mt], smem_u32p(&sAh[row][col]));
                ldsm_x4(al[mt], smem_u32p(&sAl[row][col]));
            }
            int krow = kc + (lane & 7) + ((lane >> 3) & 1) * 8;
#pragma unroll
            for (int nt = 0; nt < NT; nt++) {
                int ncol = warp_n + nt * 8;
                uint32_t bh[2], bl[2];
                ldsm_x2t(bh, smem_u32p(&sBh[krow][ncol]));
                ldsm_x2t(bl, smem_u32p(&sBl[krow][ncol]));
#pragma unroll
                for (int mt = 0; mt < MT; mt++) {
                    mma_bf16(c[mt][nt], ah[mt], bh);
                    mma_bf16(c[mt][nt], al[mt], bh);
                    mma_bf16(c[mt][nt], ah[mt], bl);
                }
            }
        }
    }

    const int g = lane >> 2, t = lane & 3;
#pragma unroll
    for (int mt = 0; mt < MT; mt++) {
        int row0 = m0 + warp_m + mt * 16 + g;
        int row1 = row0 + 8;
#pragma unroll
        for (int nt = 0; nt < NT; nt++) {
            int col = warp_n + nt * 8 + t * 2;
            float bx = 0.f, by = 0.f;
            if (BIAS) {
                float2 bb = *(const float2*)(bias + col);
                bx = bb.x; by = bb.y;
            }
            float v0 = c[mt][nt][0] + bx, v1 = c[mt][nt][1] + by;
            float v2 = c[mt][nt][2] + bx, v3 = c[mt][nt][3] + by;
            if (RELU) {
                v0 = fmaxf(v0, 0.f); v1 = fmaxf(v1, 0.f);
                v2 = fmaxf(v2, 0.f); v3 = fmaxf(v3, 0.f);
            }
            if (row0 < N_NODES)
                *(float2*)(C + (size_t)row0 * BN + col) = make_float2(v0, v1);
            if (row1 < N_NODES)
                *(float2*)(C + (size_t)row1 * BN + col) = make_float2(v2, v3);
        }
    }
}

// ---------------- launch ----------------
extern "C" void kernel_launch(void* const* d_in, const int* in_sizes, int n_in,
                              void* d_out, int out_size) {
    const float* feat = (const float*)d_in[0];
    const float* W1   = (const float*)d_in[1];
    const float* b1   = (const float*)d_in[2];
    const float* W2   = (const float*)d_in[3];
    const float* b2   = (const float*)d_in[4];
    const int*   src  = (const int*)d_in[5];
    const int*   dst  = (const int*)d_in[6];
    float*       out  = (float*)d_out;

    void *p_hn, *p_h1, *p_y2, *p_w1h, *p_w1l, *p_w2h, *p_w2l;
    cudaGetSymbolAddress(&p_hn, g_hn);
    cudaGetSymbolAddress(&p_h1, g_h1);
    cudaGetSymbolAddress(&p_y2, g_y2);
    cudaGetSymbolAddress(&p_w1h, g_W1h);
    cudaGetSymbolAddress(&p_w1l, g_W1l);
    cudaGetSymbolAddress(&p_w2h, g_W2h);
    cudaGetSymbolAddress(&p_w2l, g_W2l);
    float* hn = (float*)p_hn;
    float* h1 = (float*)p_h1;
    float* y2 = (float*)p_y2;

    // launches 1..5 (so ncu -s 5 -c 1 profiles k_agg128 at launch #6)
    k_init<<<(N_NODES + 255) / 256, 256>>>(
        W1, W2, (__nv_bfloat16*)p_w1h, (__nv_bfloat16*)p_w1l,
        (__nv_bfloat16*)p_w2h, (__nv_bfloat16*)p_w2l);
    k_hist<<<(N_EDGES + 255) / 256, 256>>>(dst);
    k_s1<<<SCAN_G, SCAN_B>>>();
    k_s3<<<SCAN_G, SCAN_B>>>();
    k_fill<<<(N_EDGES + 255) / 256, 256>>>(src, dst);

    // layer 1: aggregate feat (128 dims) -> hn
    k_agg128<<<(N_NODES * 32 + 255) / 256, 256>>>((const float4*)feat, (float4*)hn);
    // h1 = relu(hn @ W1 + b1)
    k_gemm_tc<128, true, true><<<(N_NODES + 127) / 128, 256>>>(
        hn, (__nv_bfloat16*)p_w1h, (__nv_bfloat16*)p_w1l, b1, h1);
    // layer 2 (GEMM first): y2 = h1 @ W2
    k_gemm_tc<64, false, false><<<(N_NODES + 127) / 128, 256>>>(
        h1, (__nv_bfloat16*)p_w2h, (__nv_bfloat16*)p_w2l, nullptr, y2);
    // out = (agg(y2)+y2)*inv + b2
    k_agg64<<<(N_NODES * 32 + 255) / 256, 256>>>((const float2*)y2, b2, (float2*)out);
}

// round 8
// speedup vs baseline: 2.6563x; 1.0763x over previous
#include <cuda_runtime.h>
#include <cuda_bf16.h>
#include <cstdint>

#define N_NODES 100000
#define N_EDGES 1600000
// dims: IN=128, HIDDEN=128, OUT=64

#define SCAN_B 1024
#define SCAN_G ((N_NODES + SCAN_B - 1) / SCAN_B)   // 98

// ---------------- scratch (device globals: allocation-free) ----------------
__device__ int   g_cnt[N_NODES];
__device__ int   g_off[N_NODES];
__device__ int   g_pos[N_NODES];
__device__ float g_inv[N_NODES];
__device__ int   g_blk[SCAN_G];
__device__ int   g_csr[N_EDGES];
__device__ float g_hn [N_NODES * 128];   // F' = feat @ W1
__device__ float g_h1 [N_NODES * 128];   // relu((agg(F')+F')*inv + b1)
__device__ float g_y2 [N_NODES * 64];    // h1 @ W2
__device__ __nv_bfloat16 g_W1h[128 * 128];
__device__ __nv_bfloat16 g_W1l[128 * 128];
__device__ __nv_bfloat16 g_W2h[128 * 64];
__device__ __nv_bfloat16 g_W2l[128 * 64];

// ---------------- init: zero counts + split both weight matrices ----------
__global__ void k_init(const float* __restrict__ W1,
                       const float* __restrict__ W2,
                       __nv_bfloat16* __restrict__ W1h,
                       __nv_bfloat16* __restrict__ W1l,
                       __nv_bfloat16* __restrict__ W2h,
                       __nv_bfloat16* __restrict__ W2l) {
    int i = blockIdx.x * blockDim.x + threadIdx.x;
    if (i < N_NODES) g_cnt[i] = 0;
    if (i < 128 * 128) {
        float w = W1[i];
        __nv_bfloat16 h = __float2bfloat16(w);
        W1h[i] = h;
        W1l[i] = __float2bfloat16(w - __bfloat162float(h));
    }
    if (i < 128 * 64) {
        float w = W2[i];
        __nv_bfloat16 h = __float2bfloat16(w);
        W2h[i] = h;
        W2l[i] = __float2bfloat16(w - __bfloat162float(h));
    }
}

// ---------------- histogram (4 edges per thread, int4 loads) ----------------
__global__ void k_hist(const int4* __restrict__ dst4) {
    int t = blockIdx.x * blockDim.x + threadIdx.x;
    if (t < N_EDGES / 4) {
        int4 d = dst4[t];
        atomicAdd(&g_cnt[d.x], 1);
        atomicAdd(&g_cnt[d.y], 1);
        atomicAdd(&g_cnt[d.z], 1);
        atomicAdd(&g_cnt[d.w], 1);
    }
}

// ---------------- parallel scan phase 1: block sums ----------------
__global__ void __launch_bounds__(SCAN_B)
k_s1() {
    __shared__ int sw[32];
    const int t = threadIdx.x;
    const int i = blockIdx.x * SCAN_B + t;
    int v = (i < N_NODES) ? g_cnt[i] : 0;
    int s = v;
#pragma unroll
    for (int o = 16; o > 0; o >>= 1) s += __shfl_down_sync(0xffffffffu, s, o);
    if ((t & 31) == 0) sw[t >> 5] = s;
    __syncthreads();
    if (t < 32) {
        int x = sw[t];
#pragma unroll
        for (int o = 16; o > 0; o >>= 1) x += __shfl_down_sync(0xffffffffu, x, o);
        if (t == 0) g_blk[blockIdx.x] = x;
    }
}

// ---------------- parallel scan phase 2: block prefix + local scan + apply --
__global__ void __launch_bounds__(SCAN_B)
k_s3() {
    __shared__ int sw[32];
    __shared__ int s_pref;
    __shared__ int s_blk[128];
    const int t = threadIdx.x;
    const int b = blockIdx.x;
    const int i = b * SCAN_B + t;

    if (t < 128) s_blk[t] = (t < b) ? g_blk[t] : 0;   // b <= 97 < 128
    __syncthreads();
    if (t < 64) s_blk[t] += s_blk[t + 64];
    __syncthreads();
    if (t < 32) {
        int x = s_blk[t] + s_blk[t + 32];
#pragma unroll
        for (int o = 16; o > 0; o >>= 1) x += __shfl_down_sync(0xffffffffu, x, o);
        if (t == 0) s_pref = x;
    }
    __syncthreads();

    int v = (i < N_NODES) ? g_cnt[i] : 0;
    int incl = v;
#pragma unroll
    for (int o = 1; o < 32; o <<= 1) {
        int y = __shfl_up_sync(0xffffffffu, incl, o);
        if ((t & 31) >= o) incl += y;
    }
    if ((t & 31) == 31) sw[t >> 5] = incl;
    __syncthreads();
    if (t < 32) {
        int x = sw[t];
        int xi = x;
#pragma unroll
        for (int o = 1; o < 32; o <<= 1) {
            int y = __shfl_up_sync(0xffffffffu, xi, o);
            if (t >= o) xi += y;
        }
        sw[t] = xi - x;
    }
    __syncthreads();

    if (i < N_NODES) {
        int excl = incl - v + sw[t >> 5] + s_pref;
        g_off[i] = excl;
        g_pos[i] = excl;
        g_inv[i] = 1.0f / (float)(v + 1);
    }
}

// ---------------- CSR fill (4 edges per thread, int4 loads) ----------------
__global__ void k_fill(const int4* __restrict__ src4, const int4* __restrict__ dst4) {
    int t = blockIdx.x * blockDim.x + threadIdx.x;
    if (t < N_EDGES / 4) {
        int4 s = src4[t];
        int4 d = dst4[t];
        g_csr[atomicAdd(&g_pos[d.x], 1)] = s.x;
        g_csr[atomicAdd(&g_pos[d.y], 1)] = s.y;
        g_csr[atomicAdd(&g_pos[d.z], 1)] = s.z;
        g_csr[atomicAdd(&g_pos[d.w], 1)] = s.w;
    }
}

// ---------------- aggregation 128-dim: h1 = relu((agg(F')+F')*inv + b1) ----
__global__ void __launch_bounds__(256)
k_agg128(const float4* __restrict__ x, const float* __restrict__ bias,
         float4* __restrict__ out) {
    const int warp = (blockIdx.x * blockDim.x + threadIdx.x) >> 5;
    const int lane = threadIdx.x & 31;
    if (warp >= N_NODES) return;

    const int start = g_off[warp];
    const int cnt   = g_cnt[warp];

    float4 acc = x[(size_t)warp * 32 + lane];   // self term

    for (int i0 = 0; i0 < cnt; i0 += 32) {
        const int nb = min(32, cnt - i0);
        int idx = 0;
        if (lane < nb) idx = g_csr[start + i0 + lane];

        int j = 0;
        for (; j + 8 <= nb; j += 8) {
            int s[8];
#pragma unroll
            for (int k = 0; k < 8; k++) s[k] = __shfl_sync(0xffffffffu, idx, j + k);
            float4 v[8];
#pragma unroll
            for (int k = 0; k < 8; k++) v[k] = x[(size_t)s[k] * 32 + lane];
#pragma unroll
            for (int k = 0; k < 8; k++) {
                acc.x += v[k].x; acc.y += v[k].y; acc.z += v[k].z; acc.w += v[k].w;
            }
        }
        for (; j < nb; j++) {
            int s = __shfl_sync(0xffffffffu, idx, j);
            float4 v = x[(size_t)s * 32 + lane];
            acc.x += v.x; acc.y += v.y; acc.z += v.z; acc.w += v.w;
        }
    }

    const float inv = g_inv[warp];
    float4 bb = ((const float4*)bias)[lane];
    acc.x = fmaxf(acc.x * inv + bb.x, 0.f);
    acc.y = fmaxf(acc.y * inv + bb.y, 0.f);
    acc.z = fmaxf(acc.z * inv + bb.z, 0.f);
    acc.w = fmaxf(acc.w * inv + bb.w, 0.f);
    __stcs(&out[(size_t)warp * 32 + lane], acc);
}

// ---------------- aggregation 64-dim: out = (agg(y2)+y2)*inv + b2 ----------
__global__ void __launch_bounds__(256)
k_agg64(const float2* __restrict__ x, const float* __restrict__ bias,
        float2* __restrict__ out) {
    const int warp = (blockIdx.x * blockDim.x + threadIdx.x) >> 5;
    const int lane = threadIdx.x & 31;
    if (warp >= N_NODES) return;

    const int start = g_off[warp];
    const int cnt   = g_cnt[warp];

    float2 acc = x[(size_t)warp * 32 + lane];   // self term

    for (int i0 = 0; i0 < cnt; i0 += 32) {
        const int nb = min(32, cnt - i0);
        int idx = 0;
        if (lane < nb) idx = g_csr[start + i0 + lane];

        int j = 0;
        for (; j + 8 <= nb; j += 8) {
            int s[8];
#pragma unroll
            for (int k = 0; k < 8; k++) s[k] = __shfl_sync(0xffffffffu, idx, j + k);
            float2 v[8];
#pragma unroll
            for (int k = 0; k < 8; k++) v[k] = x[(size_t)s[k] * 32 + lane];
#pragma unroll
            for (int k = 0; k < 8; k++) { acc.x += v[k].x; acc.y += v[k].y; }
        }
        for (; j < nb; j++) {
            int s = __shfl_sync(0xffffffffu, idx, j);
            float2 v = x[(size_t)s * 32 + lane];
            acc.x += v.x; acc.y += v.y;
        }
    }

    const float inv = g_inv[warp];
    float2 bb = ((const float2*)bias)[lane];
    acc.x = acc.x * inv + bb.x;
    acc.y = acc.y * inv + bb.y;
    __stcs(&out[(size_t)warp * 32 + lane], acc);
}

// ---------------- tensor-core GEMM (bf16 split, 3-pass compensated) --------
__device__ __forceinline__ uint32_t smem_u32p(const void* p) {
    return (uint32_t)__cvta_generic_to_shared(p);
}

__device__ __forceinline__ void ldsm_x4(uint32_t* r, uint32_t addr) {
    asm volatile("ldmatrix.sync.aligned.m8n8.x4.shared.b16 {%0,%1,%2,%3}, [%4];"
                 : "=r"(r[0]), "=r"(r[1]), "=r"(r[2]), "=r"(r[3]) : "r"(addr));
}
__device__ __forceinline__ void ldsm_x2t(uint32_t* r, uint32_t addr) {
    asm volatile("ldmatrix.sync.aligned.m8n8.x2.trans.shared.b16 {%0,%1}, [%2];"
                 : "=r"(r[0]), "=r"(r[1]) : "r"(addr));
}
__device__ __forceinline__ void mma_bf16(float* c, const uint32_t* a, const uint32_t* b) {
    asm volatile(
        "mma.sync.aligned.m16n8k16.row.col.f32.bf16.bf16.f32 "
        "{%0,%1,%2,%3}, {%4,%5,%6,%7}, {%8,%9}, {%0,%1,%2,%3};"
        : "+f"(c[0]), "+f"(c[1]), "+f"(c[2]), "+f"(c[3])
        : "r"(a[0]), "r"(a[1]), "r"(a[2]), "r"(a[3]), "r"(b[0]), "r"(b[1]));
}

template <int BN>
__global__ void __launch_bounds__(256)
k_gemm_tc(const float* __restrict__ A,
          const __nv_bfloat16* __restrict__ Wh,
          const __nv_bfloat16* __restrict__ Wl,
          float* __restrict__ C) {
    constexpr int K   = 128;
    constexpr int BM  = 128;
    constexpr int BK  = 32;
    constexpr int BKP = 40;
    constexpr int BNP = BN + 8;
    constexpr int WNT = BN / 2;
    constexpr int NT  = WNT / 8;
    constexpr int MT  = 2;

    __shared__ __align__(16) __nv_bfloat16 sAh[BM][BKP];
    __shared__ __align__(16) __nv_bfloat16 sAl[BM][BKP];
    __shared__ __align__(16) __nv_bfloat16 sBh[BK][BNP];
    __shared__ __align__(16) __nv_bfloat16 sBl[BK][BNP];

    const int tid  = threadIdx.x;
    const int lane = tid & 31;
    const int wid  = tid >> 5;
    const int wm   = wid & 3;
    const int wn   = wid >> 2;
    const int m0   = blockIdx.x * BM;
    const int warp_m = wm * 32;
    const int warp_n = wn * WNT;

    float c[MT][NT][4];
#pragma unroll
    for (int mt = 0; mt < MT; mt++)
#pragma unroll
        for (int nt = 0; nt < NT; nt++)
#pragma unroll
            for (int j = 0; j < 4; j++) c[mt][nt][j] = 0.0f;

    for (int k0 = 0; k0 < K; k0 += BK) {
        if (k0) __syncthreads();
        // ---- load + split A tile (streaming: evict-first) ----
        {
            const int r  = tid >> 3;
            const int c4 = tid & 7;
#pragma unroll
            for (int i = 0; i < 4; i++) {
                int row = r + i * 32;
                int m   = m0 + row;
                float4 v = make_float4(0.f, 0.f, 0.f, 0.f);
                if (m < N_NODES)
                    v = __ldcs((const float4*)(A + (size_t)m * K + k0 + c4 * 4));
                float f[4] = {v.x, v.y, v.z, v.w};
#pragma unroll
                for (int j = 0; j < 4; j++) {
                    __nv_bfloat16 h = __float2bfloat16(f[j]);
                    sAh[row][c4 * 4 + j] = h;
                    sAl[row][c4 * 4 + j] = __float2bfloat16(f[j] - __bfloat162float(h));
                }
            }
        }
        // ---- load W tile (pre-split bf16, row-major [K][BN]) ----
        {
            constexpr int PAIRS = BK * BN / 2;
            constexpr int PER   = PAIRS / 256;
#pragma unroll
            for (int i = 0; i < PER; i++) {
                int p  = tid + i * 256;
                int k  = p / (BN / 2);
                int n2 = p % (BN / 2);
                uint32_t vh = ((const uint32_t*)Wh)[(size_t)(k0 + k) * (BN / 2) + n2];
                uint32_t vl = ((const uint32_t*)Wl)[(size_t)(k0 + k) * (BN / 2) + n2];
                *(uint32_t*)&sBh[k][n2 * 2] = vh;
                *(uint32_t*)&sBl[k][n2 * 2] = vl;
            }
        }
        __syncthreads();

#pragma unroll
        for (int kc = 0; kc < BK; kc += 16) {
            uint32_t ah[MT][4], al[MT][4];
#pragma unroll
            for (int mt = 0; mt < MT; mt++) {
                int row = warp_m + mt * 16 + (lane & 15);
                int col = kc + (lane >> 4) * 8;
                ldsm_x4(ah[mt], smem_u32p(&sAh[row][col]));
                ldsm_x4(al[mt], smem_u32p(&sAl[row][col]));
            }
            int krow = kc + (lane & 7) + ((lane >> 3) & 1) * 8;
#pragma unroll
            for (int nt = 0; nt < NT; nt++) {
                int ncol = warp_n + nt * 8;
                uint32_t bh[2], bl[2];
                ldsm_x2t(bh, smem_u32p(&sBh[krow][ncol]));
                ldsm_x2t(bl, smem_u32p(&sBl[krow][ncol]));
#pragma unroll
                for (int mt = 0; mt < MT; mt++) {
                    mma_bf16(c[mt][nt], ah[mt], bh);
                    mma_bf16(c[mt][nt], al[mt], bh);
                    mma_bf16(c[mt][nt], ah[mt], bl);
                }
            }
        }
    }

    const int g = lane >> 2, t = lane & 3;
#pragma unroll
    for (int mt = 0; mt < MT; mt++) {
        int row0 = m0 + warp_m + mt * 16 + g;
        int row1 = row0 + 8;
#pragma unroll
        for (int nt = 0; nt < NT; nt++) {
            int col = warp_n + nt * 8 + t * 2;
            if (row0 < N_NODES)
                *(float2*)(C + (size_t)row0 * BN + col) = make_float2(c[mt][nt][0], c[mt][nt][1]);
            if (row1 < N_NODES)
                *(float2*)(C + (size_t)row1 * BN + col) = make_float2(c[mt][nt][2], c[mt][nt][3]);
        }
    }
}

// ---------------- launch ----------------
extern "C" void kernel_launch(void* const* d_in, const int* in_sizes, int n_in,
                              void* d_out, int out_size) {
    const float* feat = (const float*)d_in[0];
    const float* W1   = (const float*)d_in[1];
    const float* b1   = (const float*)d_in[2];
    const float* W2   = (const float*)d_in[3];
    const float* b2   = (const float*)d_in[4];
    const int*   src  = (const int*)d_in[5];
    const int*   dst  = (const int*)d_in[6];
    float*       out  = (float*)d_out;

    void *p_hn, *p_h1, *p_y2, *p_w1h, *p_w1l, *p_w2h, *p_w2l;
    cudaGetSymbolAddress(&p_hn, g_hn);
    cudaGetSymbolAddress(&p_h1, g_h1);
    cudaGetSymbolAddress(&p_y2, g_y2);
    cudaGetSymbolAddress(&p_w1h, g_W1h);
    cudaGetSymbolAddress(&p_w1l, g_W1l);
    cudaGetSymbolAddress(&p_w2h, g_W2h);
    cudaGetSymbolAddress(&p_w2l, g_W2l);
    float* hn = (float*)p_hn;   // F' = feat @ W1
    float* h1 = (float*)p_h1;
    float* y2 = (float*)p_y2;

    // lazy side-stream + events (host-side infra only; device work identical every call)
    static cudaStream_t s_side = nullptr;
    static cudaEvent_t  e0 = nullptr, e1 = nullptr;
    static bool stream_ok = false;
    if (!s_side) {
        stream_ok =
            (cudaStreamCreateWithFlags(&s_side, cudaStreamNonBlocking) == cudaSuccess) &&
            (cudaEventCreateWithFlags(&e0, cudaEventDisableTiming) == cudaSuccess) &&
            (cudaEventCreateWithFlags(&e1, cudaEventDisableTiming) == cudaSuccess);
    }

    // init: zero counts + split weights (needed by both branches)
    k_init<<<(N_NODES + 255) / 256, 256>>>(
        W1, W2, (__nv_bfloat16*)p_w1h, (__nv_bfloat16*)p_w1l,
        (__nv_bfloat16*)p_w2h, (__nv_bfloat16*)p_w2l);

    if (stream_ok) {
        // fork: GEMM1 (feat @ W1 -> F') on side stream, CSR build on main
        cudaEventRecord(e0, 0);
        cudaStreamWaitEvent(s_side, e0, 0);
        k_gemm_tc<128><<<(N_NODES + 127) / 128, 256, 0, s_side>>>(
            feat, (__nv_bfloat16*)p_w1h, (__nv_bfloat16*)p_w1l, hn);
        cudaEventRecord(e1, s_side);
    }

    // CSR build on main stream
    k_hist<<<(N_EDGES / 4 + 255) / 256, 256>>>((const int4*)dst);
    k_s1<<<SCAN_G, SCAN_B>>>();
    k_s3<<<SCAN_G, SCAN_B>>>();
    k_fill<<<(N_EDGES / 4 + 255) / 256, 256>>>((const int4*)src, (const int4*)dst);

    if (stream_ok) {
        cudaStreamWaitEvent(0, e1, 0);   // join: F' ready
    } else {
        // serial fallback
        k_gemm_tc<128><<<(N_NODES + 127) / 128, 256>>>(
            feat, (__nv_bfloat16*)p_w1h, (__nv_bfloat16*)p_w1l, hn);
    }

    // h1 = relu((agg(F') + F') * inv + b1)
    k_agg128<<<(N_NODES * 32 + 255) / 256, 256>>>((const float4*)hn, b1, (float4*)h1);
    // y2 = h1 @ W2
    k_gemm_tc<64><<<(N_NODES + 127) / 128, 256>>>(
        h1, (__nv_bfloat16*)p_w2h, (__nv_bfloat16*)p_w2l, y2);
    // out = (agg(y2) + y2) * inv + b2
    k_agg64<<<(N_NODES * 32 + 255) / 256, 256>>>((const float2*)y2, b2, (float2*)out);
}

// round 9
// speedup vs baseline: 3.0592x; 1.1517x over previous
#include <cuda_runtime.h>
#include <cuda_bf16.h>
#include <cuda_fp16.h>
#include <cstdint>

#define N_NODES 100000
#define N_EDGES 1600000
// dims: IN=128, HIDDEN=128, OUT=64

#define SCAN_B 1024
#define SCAN_G ((N_NODES + SCAN_B - 1) / SCAN_B)   // 98

// ---------------- scratch (device globals: allocation-free) ----------------
__device__ int    g_cnt[N_NODES];
__device__ int    g_off[N_NODES];
__device__ int    g_pos[N_NODES];
__device__ float  g_inv[N_NODES];
__device__ int    g_blk[SCAN_G];
__device__ int    g_csr[N_EDGES];
__device__ __half g_hn [N_NODES * 128];   // F' = feat @ W1            (fp16)
__device__ __half g_h1 [N_NODES * 128];   // relu((agg+self)*inv + b1) (fp16)
__device__ __half g_y2 [N_NODES * 64];    // h1 @ W2                   (fp16)
__device__ __nv_bfloat16 g_W1h[128 * 128];
__device__ __nv_bfloat16 g_W1l[128 * 128];
__device__ __nv_bfloat16 g_W2h[128 * 64];
__device__ __nv_bfloat16 g_W2l[128 * 64];

// ---------------- init: zero counts + split both weight matrices ----------
__global__ void k_init(const float* __restrict__ W1,
                       const float* __restrict__ W2,
                       __nv_bfloat16* __restrict__ W1h,
                       __nv_bfloat16* __restrict__ W1l,
                       __nv_bfloat16* __restrict__ W2h,
                       __nv_bfloat16* __restrict__ W2l) {
    int i = blockIdx.x * blockDim.x + threadIdx.x;
    if (i < N_NODES) g_cnt[i] = 0;
    if (i < 128 * 128) {
        float w = W1[i];
        __nv_bfloat16 h = __float2bfloat16(w);
        W1h[i] = h;
        W1l[i] = __float2bfloat16(w - __bfloat162float(h));
    }
    if (i < 128 * 64) {
        float w = W2[i];
        __nv_bfloat16 h = __float2bfloat16(w);
        W2h[i] = h;
        W2l[i] = __float2bfloat16(w - __bfloat162float(h));
    }
}

// ---------------- histogram (4 edges per thread, int4 loads) ----------------
__global__ void k_hist(const int4* __restrict__ dst4) {
    int t = blockIdx.x * blockDim.x + threadIdx.x;
    if (t < N_EDGES / 4) {
        int4 d = dst4[t];
        atomicAdd(&g_cnt[d.x], 1);
        atomicAdd(&g_cnt[d.y], 1);
        atomicAdd(&g_cnt[d.z], 1);
        atomicAdd(&g_cnt[d.w], 1);
    }
}

// ---------------- parallel scan phase 1: block sums ----------------
__global__ void __launch_bounds__(SCAN_B)
k_s1() {
    __shared__ int sw[32];
    const int t = threadIdx.x;
    const int i = blockIdx.x * SCAN_B + t;
    int v = (i < N_NODES) ? g_cnt[i] : 0;
    int s = v;
#pragma unroll
    for (int o = 16; o > 0; o >>= 1) s += __shfl_down_sync(0xffffffffu, s, o);
    if ((t & 31) == 0) sw[t >> 5] = s;
    __syncthreads();
    if (t < 32) {
        int x = sw[t];
#pragma unroll
        for (int o = 16; o > 0; o >>= 1) x += __shfl_down_sync(0xffffffffu, x, o);
        if (t == 0) g_blk[blockIdx.x] = x;
    }
}

// ---------------- parallel scan phase 2: block prefix + local scan + apply --
__global__ void __launch_bounds__(SCAN_B)
k_s3() {
    __shared__ int sw[32];
    __shared__ int s_pref;
    __shared__ int s_blk[128];
    const int t = threadIdx.x;
    const int b = blockIdx.x;
    const int i = b * SCAN_B + t;

    if (t < 128) s_blk[t] = (t < b) ? g_blk[t] : 0;   // b <= 97 < 128
    __syncthreads();
    if (t < 64) s_blk[t] += s_blk[t + 64];
    __syncthreads();
    if (t < 32) {
        int x = s_blk[t] + s_blk[t + 32];
#pragma unroll
        for (int o = 16; o > 0; o >>= 1) x += __shfl_down_sync(0xffffffffu, x, o);
        if (t == 0) s_pref = x;
    }
    __syncthreads();

    int v = (i < N_NODES) ? g_cnt[i] : 0;
    int incl = v;
#pragma unroll
    for (int o = 1; o < 32; o <<= 1) {
        int y = __shfl_up_sync(0xffffffffu, incl, o);
        if ((t & 31) >= o) incl += y;
    }
    if ((t & 31) == 31) sw[t >> 5] = incl;
    __syncthreads();
    if (t < 32) {
        int x = sw[t];
        int xi = x;
#pragma unroll
        for (int o = 1; o < 32; o <<= 1) {
            int y = __shfl_up_sync(0xffffffffu, xi, o);
            if (t >= o) xi += y;
        }
        sw[t] = xi - x;
    }
    __syncthreads();

    if (i < N_NODES) {
        int excl = incl - v + sw[t >> 5] + s_pref;
        g_off[i] = excl;
        g_pos[i] = excl;
        g_inv[i] = 1.0f / (float)(v + 1);
    }
}

// ---------------- CSR fill (4 edges per thread, int4 loads) ----------------
__global__ void k_fill(const int4* __restrict__ src4, const int4* __restrict__ dst4) {
    int t = blockIdx.x * blockDim.x + threadIdx.x;
    if (t < N_EDGES / 4) {
        int4 s = src4[t];
        int4 d = dst4[t];
        g_csr[atomicAdd(&g_pos[d.x], 1)] = s.x;
        g_csr[atomicAdd(&g_pos[d.y], 1)] = s.y;
        g_csr[atomicAdd(&g_pos[d.z], 1)] = s.z;
        g_csr[atomicAdd(&g_pos[d.w], 1)] = s.w;
    }
}

// ---------------- agg128 (fp16 in/out): h1 = relu((agg(F')+F')*inv + b1) ---
// rows = 128 halves = 32 uint2 per row; each lane owns 4 dims (one uint2)
__global__ void __launch_bounds__(256)
k_agg128h(const uint2* __restrict__ x, const float* __restrict__ bias,
          uint2* __restrict__ out) {
    const int warp = (blockIdx.x * blockDim.x + threadIdx.x) >> 5;
    const int lane = threadIdx.x & 31;
    if (warp >= N_NODES) return;

    const int start = g_off[warp];
    const int cnt   = g_cnt[warp];

    float4 acc;
    {
        uint2 raw = x[(size_t)warp * 32 + lane];   // self term
        float2 a = __half22float2(*(const __half2*)&raw.x);
        float2 b = __half22float2(*(const __half2*)&raw.y);
        acc = make_float4(a.x, a.y, b.x, b.y);
    }

    for (int i0 = 0; i0 < cnt; i0 += 32) {
        const int nb = min(32, cnt - i0);
        int idx = 0;
        if (lane < nb) idx = g_csr[start + i0 + lane];

        int j = 0;
        for (; j + 8 <= nb; j += 8) {
            int s[8];
#pragma unroll
            for (int k = 0; k < 8; k++) s[k] = __shfl_sync(0xffffffffu, idx, j + k);
            uint2 v[8];
#pragma unroll
            for (int k = 0; k < 8; k++) v[k] = x[(size_t)s[k] * 32 + lane];
#pragma unroll
            for (int k = 0; k < 8; k++) {
                float2 a = __half22float2(*(const __half2*)&v[k].x);
                float2 b = __half22float2(*(const __half2*)&v[k].y);
                acc.x += a.x; acc.y += a.y; acc.z += b.x; acc.w += b.y;
            }
        }
        for (; j < nb; j++) {
            int s = __shfl_sync(0xffffffffu, idx, j);
            uint2 v = x[(size_t)s * 32 + lane];
            float2 a = __half22float2(*(const __half2*)&v.x);
            float2 b = __half22float2(*(const __half2*)&v.y);
            acc.x += a.x; acc.y += a.y; acc.z += b.x; acc.w += b.y;
        }
    }

    const float inv = g_inv[warp];
    float4 bb = ((const float4*)bias)[lane];
    acc.x = fmaxf(acc.x * inv + bb.x, 0.f);
    acc.y = fmaxf(acc.y * inv + bb.y, 0.f);
    acc.z = fmaxf(acc.z * inv + bb.z, 0.f);
    acc.w = fmaxf(acc.w * inv + bb.w, 0.f);
    uint2 o;
    *(__half2*)&o.x = __floats2half2_rn(acc.x, acc.y);
    *(__half2*)&o.y = __floats2half2_rn(acc.z, acc.w);
    __stcs(&out[(size_t)warp * 32 + lane], o);
}

// ---------------- agg64 (fp16 in, fp32 out): out = (agg(y2)+y2)*inv + b2 ---
// rows = 64 halves = 32 half2 per row; lane owns 2 dims
__global__ void __launch_bounds__(256)
k_agg64h(const uint32_t* __restrict__ x, const float* __restrict__ bias,
         float2* __restrict__ out) {
    const int warp = (blockIdx.x * blockDim.x + threadIdx.x) >> 5;
    const int lane = threadIdx.x & 31;
    if (warp >= N_NODES) return;

    const int start = g_off[warp];
    const int cnt   = g_cnt[warp];

    float2 acc;
    {
        uint32_t raw = x[(size_t)warp * 32 + lane];   // self term
        acc = __half22float2(*(const __half2*)&raw);
    }

    for (int i0 = 0; i0 < cnt; i0 += 32) {
        const int nb = min(32, cnt - i0);
        int idx = 0;
        if (lane < nb) idx = g_csr[start + i0 + lane];

        int j = 0;
        for (; j + 8 <= nb; j += 8) {
            int s[8];
#pragma unroll
            for (int k = 0; k < 8; k++) s[k] = __shfl_sync(0xffffffffu, idx, j + k);
            uint32_t v[8];
#pragma unroll
            for (int k = 0; k < 8; k++) v[k] = x[(size_t)s[k] * 32 + lane];
#pragma unroll
            for (int k = 0; k < 8; k++) {
                float2 f = __half22float2(*(const __half2*)&v[k]);
                acc.x += f.x; acc.y += f.y;
            }
        }
        for (; j < nb; j++) {
            int s = __shfl_sync(0xffffffffu, idx, j);
            uint32_t v = x[(size_t)s * 32 + lane];
            float2 f = __half22float2(*(const __half2*)&v);
            acc.x += f.x; acc.y += f.y;
        }
    }

    const float inv = g_inv[warp];
    float2 bb = ((const float2*)bias)[lane];
    acc.x = acc.x * inv + bb.x;
    acc.y = acc.y * inv + bb.y;
    __stcs(&out[(size_t)warp * 32 + lane], acc);
}

// ---------------- tensor-core GEMM (bf16 split, 3-pass compensated) --------
__device__ __forceinline__ uint32_t smem_u32p(const void* p) {
    return (uint32_t)__cvta_generic_to_shared(p);
}

__device__ __forceinline__ void ldsm_x4(uint32_t* r, uint32_t addr) {
    asm volatile("ldmatrix.sync.aligned.m8n8.x4.shared.b16 {%0,%1,%2,%3}, [%4];"
                 : "=r"(r[0]), "=r"(r[1]), "=r"(r[2]), "=r"(r[3]) : "r"(addr));
}
__device__ __forceinline__ void ldsm_x2t(uint32_t* r, uint32_t addr) {
    asm volatile("ldmatrix.sync.aligned.m8n8.x2.trans.shared.b16 {%0,%1}, [%2];"
                 : "=r"(r[0]), "=r"(r[1]) : "r"(addr));
}
__device__ __forceinline__ void mma_bf16(float* c, const uint32_t* a, const uint32_t* b) {
    asm volatile(
        "mma.sync.aligned.m16n8k16.row.col.f32.bf16.bf16.f32 "
        "{%0,%1,%2,%3}, {%4,%5,%6,%7}, {%8,%9}, {%0,%1,%2,%3};"
        : "+f"(c[0]), "+f"(c[1]), "+f"(c[2]), "+f"(c[3])
        : "r"(a[0]), "r"(a[1]), "r"(a[2]), "r"(a[3]), "r"(b[0]), "r"(b[1]));
}

// A-row quad loaders (4 consecutive elems at p), streaming
__device__ __forceinline__ void loadA4(const float* p, float* f) {
    float4 v = __ldcs((const float4*)p);
    f[0] = v.x; f[1] = v.y; f[2] = v.z; f[3] = v.w;
}
__device__ __forceinline__ void loadA4(const __half* p, float* f) {
    uint2 u = __ldcs((const uint2*)p);
    float2 a = __half22float2(*(const __half2*)&u.x);
    float2 b = __half22float2(*(const __half2*)&u.y);
    f[0] = a.x; f[1] = a.y; f[2] = b.x; f[3] = b.y;
}

template <int BN, typename TIn>
__global__ void __launch_bounds__(256)
k_gemm_tc(const TIn* __restrict__ A,
          const __nv_bfloat16* __restrict__ Wh,
          const __nv_bfloat16* __restrict__ Wl,
          __half* __restrict__ C) {
    constexpr int K   = 128;
    constexpr int BM  = 128;
    constexpr int BK  = 32;
    constexpr int BKP = 40;
    constexpr int BNP = BN + 8;
    constexpr int WNT = BN / 2;
    constexpr int NT  = WNT / 8;
    constexpr int MT  = 2;

    __shared__ __align__(16) __nv_bfloat16 sAh[BM][BKP];
    __shared__ __align__(16) __nv_bfloat16 sAl[BM][BKP];
    __shared__ __align__(16) __nv_bfloat16 sBh[BK][BNP];
    __shared__ __align__(16) __nv_bfloat16 sBl[BK][BNP];

    const int tid  = threadIdx.x;
    const int lane = tid & 31;
    const int wid  = tid >> 5;
    const int wm   = wid & 3;
    const int wn   = wid >> 2;
    const int m0   = blockIdx.x * BM;
    const int warp_m = wm * 32;
    const int warp_n = wn * WNT;

    float c[MT][NT][4];
#pragma unroll
    for (int mt = 0; mt < MT; mt++)
#pragma unroll
        for (int nt = 0; nt < NT; nt++)
#pragma unroll
            for (int j = 0; j < 4; j++) c[mt][nt][j] = 0.0f;

    for (int k0 = 0; k0 < K; k0 += BK) {
        if (k0) __syncthreads();
        // ---- load + split A tile ----
        {
            const int r  = tid >> 3;
            const int c4 = tid & 7;
#pragma unroll
            for (int i = 0; i < 4; i++) {
                int row = r + i * 32;
                int m   = m0 + row;
                float f[4] = {0.f, 0.f, 0.f, 0.f};
                if (m < N_NODES)
                    loadA4(A + (size_t)m * K + k0 + c4 * 4, f);
#pragma unroll
                for (int j = 0; j < 4; j++) {
                    __nv_bfloat16 h = __float2bfloat16(f[j]);
                    sAh[row][c4 * 4 + j] = h;
                    sAl[row][c4 * 4 + j] = __float2bfloat16(f[j] - __bfloat162float(h));
                }
            }
        }
        // ---- load W tile (pre-split bf16, row-major [K][BN]) ----
        {
            constexpr int PAIRS = BK * BN / 2;
            constexpr int PER   = PAIRS / 256;
#pragma unroll
            for (int i = 0; i < PER; i++) {
                int p  = tid + i * 256;
                int k  = p / (BN / 2);
                int n2 = p % (BN / 2);
                uint32_t vh = ((const uint32_t*)Wh)[(size_t)(k0 + k) * (BN / 2) + n2];
                uint32_t vl = ((const uint32_t*)Wl)[(size_t)(k0 + k) * (BN / 2) + n2];
                *(uint32_t*)&sBh[k][n2 * 2] = vh;
                *(uint32_t*)&sBl[k][n2 * 2] = vl;
            }
        }
        __syncthreads();

#pragma unroll
        for (int kc = 0; kc < BK; kc += 16) {
            uint32_t ah[MT][4], al[MT][4];
#pragma unroll
            for (int mt = 0; mt < MT; mt++) {
                int row = warp_m + mt * 16 + (lane & 15);
                int col = kc + (lane >> 4) * 8;
                ldsm_x4(ah[mt], smem_u32p(&sAh[row][col]));
                ldsm_x4(al[mt], smem_u32p(&sAl[row][col]));
            }
            int krow = kc + (lane & 7) + ((lane >> 3) & 1) * 8;
#pragma unroll
            for (int nt = 0; nt < NT; nt++) {
                int ncol = warp_n + nt * 8;
                uint32_t bh[2], bl[2];
                ldsm_x2t(bh, smem_u32p(&sBh[krow][ncol]));
                ldsm_x2t(bl, smem_u32p(&sBl[krow][ncol]));
#pragma unroll
                for (int mt = 0; mt < MT; mt++) {
                    mma_bf16(c[mt][nt], ah[mt], bh);
                    mma_bf16(c[mt][nt], al[mt], bh);
                    mma_bf16(c[mt][nt], ah[mt], bl);
                }
            }
        }
    }

    const int g = lane >> 2, t = lane & 3;
#pragma unroll
    for (int mt = 0; mt < MT; mt++) {
        int row0 = m0 + warp_m + mt * 16 + g;
        int row1 = row0 + 8;
#pragma unroll
        for (int nt = 0; nt < NT; nt++) {
            int col = warp_n + nt * 8 + t * 2;
            if (row0 < N_NODES)
                *(__half2*)(C + (size_t)row0 * BN + col) =
                    __floats2half2_rn(c[mt][nt][0], c[mt][nt][1]);
            if (row1 < N_NODES)
                *(__half2*)(C + (size_t)row1 * BN + col) =
                    __floats2half2_rn(c[mt][nt][2], c[mt][nt][3]);
        }
    }
}

// ---------------- launch ----------------
extern "C" void kernel_launch(void* const* d_in, const int* in_sizes, int n_in,
                              void* d_out, int out_size) {
    const float* feat = (const float*)d_in[0];
    const float* W1   = (const float*)d_in[1];
    const float* b1   = (const float*)d_in[2];
    const float* W2   = (const float*)d_in[3];
    const float* b2   = (const float*)d_in[4];
    const int*   src  = (const int*)d_in[5];
    const int*   dst  = (const int*)d_in[6];
    float*       out  = (float*)d_out;

    void *p_hn, *p_h1, *p_y2, *p_w1h, *p_w1l, *p_w2h, *p_w2l;
    cudaGetSymbolAddress(&p_hn, g_hn);
    cudaGetSymbolAddress(&p_h1, g_h1);
    cudaGetSymbolAddress(&p_y2, g_y2);
    cudaGetSymbolAddress(&p_w1h, g_W1h);
    cudaGetSymbolAddress(&p_w1l, g_W1l);
    cudaGetSymbolAddress(&p_w2h, g_W2h);
    cudaGetSymbolAddress(&p_w2l, g_W2l);
    __half* hn = (__half*)p_hn;   // F' = feat @ W1 (fp16)
    __half* h1 = (__half*)p_h1;
    __half* y2 = (__half*)p_y2;

    // lazy side-stream + events (host-side infra only)
    static cudaStream_t s_side = nullptr;
    static cudaEvent_t  e0 = nullptr, e1 = nullptr;
    static bool stream_ok = false;
    if (!s_side) {
        stream_ok =
            (cudaStreamCreateWithFlags(&s_side, cudaStreamNonBlocking) == cudaSuccess) &&
            (cudaEventCreateWithFlags(&e0, cudaEventDisableTiming) == cudaSuccess) &&
            (cudaEventCreateWithFlags(&e1, cudaEventDisableTiming) == cudaSuccess);
    }

    // init: zero counts + split weights
    k_init<<<(N_NODES + 255) / 256, 256>>>(
        W1, W2, (__nv_bfloat16*)p_w1h, (__nv_bfloat16*)p_w1l,
        (__nv_bfloat16*)p_w2h, (__nv_bfloat16*)p_w2l);

    if (stream_ok) {
        // fork: GEMM1 (feat @ W1 -> F' fp16) on side stream, CSR build on main
        cudaEventRecord(e0, 0);
        cudaStreamWaitEvent(s_side, e0, 0);
        k_gemm_tc<128, float><<<(N_NODES + 127) / 128, 256, 0, s_side>>>(
            feat, (__nv_bfloat16*)p_w1h, (__nv_bfloat16*)p_w1l, hn);
        cudaEventRecord(e1, s_side);
    }

    // CSR build on main stream
    k_hist<<<(N_EDGES / 4 + 255) / 256, 256>>>((const int4*)dst);
    k_s1<<<SCAN_G, SCAN_B>>>();
    k_s3<<<SCAN_G, SCAN_B>>>();
    k_fill<<<(N_EDGES / 4 + 255) / 256, 256>>>((const int4*)src, (const int4*)dst);

    if (stream_ok) {
        cudaStreamWaitEvent(0, e1, 0);   // join: F' ready
    } else {
        k_gemm_tc<128, float><<<(N_NODES + 127) / 128, 256>>>(
            feat, (__nv_bfloat16*)p_w1h, (__nv_bfloat16*)p_w1l, hn);
    }

    // h1 = relu((agg(F') + F') * inv + b1)   (fp16 gather)
    k_agg128h<<<(N_NODES * 32 + 255) / 256, 256>>>((const uint2*)hn, b1, (uint2*)h1);
    // y2 = h1 @ W2   (fp16 in/out)
    k_gemm_tc<64, __half><<<(N_NODES + 127) / 128, 256>>>(
        h1, (__nv_bfloat16*)p_w2h, (__nv_bfloat16*)p_w2l, y2);
    // out = (agg(y2) + y2) * inv + b2   (fp16 gather, fp32 out)
    k_agg64h<<<(N_NODES * 32 + 255) / 256, 256>>>((const uint32_t*)y2, b2, (float2*)out);
}